// round 8
// baseline (speedup 1.0000x reference)
#include <cuda_runtime.h>
#include <cuda_fp16.h>
#include <mma.h>
#include <cstdint>

using namespace nvcuda;

#define N_NODES 100000
#define N_EDGESC 1600000
#define XDIM 1010
#define SUBJ 1000
#define H1 512
#define H2 256
#define DG 128

// ---------------- static device scratch ----------------
__device__ __half g_xs[(size_t)N_NODES * 2048];   // x split: [row][0..1023]=hi, [1024..2047]=lo
__device__ __half g_w1h[1024 * H1];               // W1 hi only (2-term GEMM1)
__device__ __half g_hs[(size_t)N_NODES * 1024];   // h split: [0..511]=hi, [512..1023]=lo
__device__ __half g_w23h[H1 * DG];
__device__ __half g_w23l[H1 * DG];
__device__ float  g_c2[DG];
__device__ float  g_y[(size_t)N_NODES * DG];
__device__ int    g_deg[N_NODES];
__device__ int    g_off[N_NODES];
__device__ int    g_cur[N_NODES];
__device__ int    g_es[N_EDGESC];
__device__ int    g_bsum[128];
__device__ double g_acc;

// ---------------- helpers ----------------
__device__ __forceinline__ uint32_t smem_u32(const void* p) {
    uint32_t a;
    asm("{ .reg .u64 t; cvta.to.shared.u64 t, %1; cvt.u32.u64 %0, t; }" : "=r"(a) : "l"(p));
    return a;
}
#define CP_A16(dst, src, n) \
    asm volatile("cp.async.cg.shared.global [%0], [%1], 16, %2;" :: "r"(dst), "l"(src), "r"(n))
#define CP_COMMIT() asm volatile("cp.async.commit_group;" ::: "memory")
#define CP_WAIT0()  asm volatile("cp.async.wait_group 0;" ::: "memory")
#define CP_WAIT1()  asm volatile("cp.async.wait_group 1;" ::: "memory")

__device__ __forceinline__ void split_h2(float2 v, __half2& hi, __half2& lo) {
    hi = __float22half2_rn(v);
    float2 l = make_float2(v.x - __half2float(__low2half(hi)),
                           v.y - __half2float(__high2half(hi)));
    lo = __float22half2_rn(l);
}

// ---------------- pre-split x ----------------
__global__ void k_splitx(const float* __restrict__ x) {
    for (long long id = (long long)blockIdx.x * blockDim.x + threadIdx.x;
         id < (long long)N_NODES * 512; id += (long long)gridDim.x * blockDim.x) {
        int row = (int)(id >> 9);
        int c2 = (int)(id & 511);
        int col = c2 * 2;
        float2 v = make_float2(0.f, 0.f);
        if (col < SUBJ) v = *reinterpret_cast<const float2*>(&x[(size_t)row * XDIM + col]);
        __half2 hi, lo;
        split_h2(v, hi, lo);
        *reinterpret_cast<__half2*>(&g_xs[(size_t)row * 2048 + col]) = hi;
        *reinterpret_cast<__half2*>(&g_xs[(size_t)row * 2048 + 1024 + col]) = lo;
    }
}

// ---------------- W1 -> fp16 (hi only) ----------------
__global__ void k_splitw(const float* __restrict__ W1) {
    int id = blockIdx.x * blockDim.x + threadIdx.x;
    if (id >= 1024 * 256) return;
    int row = id >> 8;
    int col = (id & 255) * 2;
    float2 v = make_float2(0.f, 0.f);
    if (row < SUBJ) v = *reinterpret_cast<const float2*>(&W1[(size_t)row * H1 + col]);
    *reinterpret_cast<__half2*>(&g_w1h[row * H1 + col]) = __float22half2_rn(v);
}

// ---------------- init ----------------
__global__ void k_init() {
    int i = blockIdx.x * blockDim.x + threadIdx.x;
    if (i < N_NODES) g_deg[i] = 1;
    if (i == 0) g_acc = 0.0;
}

// ---------------- weight fold (split fp16) ----------------
__global__ void k_pre(const float* __restrict__ W2, const float* __restrict__ Wg,
                      const float* __restrict__ b2) {
    int k = blockIdx.x;
    int j = threadIdx.x;
    if (k < H1) {
        __shared__ float row[H2];
        for (int m = j; m < H2; m += 128) row[m] = W2[k * H2 + m];
        __syncthreads();
        float acc = 0.f;
        #pragma unroll 4
        for (int m = 0; m < H2; m++) acc += row[m] * Wg[m * DG + j];
        __half h = __float2half_rn(acc);
        g_w23h[k * DG + j] = h;
        g_w23l[k * DG + j] = __float2half_rn(acc - __half2float(h));
    } else {
        float acc = 0.f;
        for (int m = 0; m < H2; m++) acc += b2[m] * Wg[m * DG + j];
        g_c2[j] = acc;
    }
}

// ---------------- degree count ----------------
__global__ void k_deg(const int* __restrict__ ei) {
    for (int e = blockIdx.x * blockDim.x + threadIdx.x; e < N_EDGESC;
         e += gridDim.x * blockDim.x) {
        int dst = ei[N_EDGESC + e];
        dst = min(max(dst, 0), N_NODES - 1);
        atomicAdd(&g_deg[dst], 1);
    }
}

// ---------------- multi-block scan ----------------
#define SCAN_CHUNK 1024
#define SCAN_NBLK ((N_NODES + SCAN_CHUNK - 1) / SCAN_CHUNK)  // 98

__global__ void k_scan1() {
    __shared__ int wsum[32];
    int i = blockIdx.x * SCAN_CHUNK + threadIdx.x;
    int v = (i < N_NODES) ? (g_deg[i] - 1) : 0;
    #pragma unroll
    for (int o = 16; o; o >>= 1) v += __shfl_down_sync(0xffffffffu, v, o);
    int lane = threadIdx.x & 31, wid = threadIdx.x >> 5;
    if (lane == 0) wsum[wid] = v;
    __syncthreads();
    if (wid == 0) {
        int t = wsum[lane];
        #pragma unroll
        for (int o = 16; o; o >>= 1) t += __shfl_down_sync(0xffffffffu, t, o);
        if (lane == 0) g_bsum[blockIdx.x] = t;
    }
}

__global__ void k_scan2() {
    __shared__ int wtot[4];
    int tid = threadIdx.x, lane = tid & 31, wid = tid >> 5;
    int v = (tid < SCAN_NBLK) ? g_bsum[tid] : 0;
    int s = v;
    #pragma unroll
    for (int o = 1; o < 32; o <<= 1) {
        int t = __shfl_up_sync(0xffffffffu, s, o);
        if (lane >= o) s += t;
    }
    if (lane == 31) wtot[wid] = s;
    __syncthreads();
    int base = 0;
    for (int w = 0; w < wid; w++) base += wtot[w];
    if (tid < SCAN_NBLK) g_bsum[tid] = base + s - v;
}

__global__ void k_scan3() {
    __shared__ int wpre[32];
    int tid = threadIdx.x, lane = tid & 31, wid = tid >> 5;
    int i = blockIdx.x * SCAN_CHUNK + tid;
    int v = (i < N_NODES) ? (g_deg[i] - 1) : 0;
    int s = v;
    #pragma unroll
    for (int o = 1; o < 32; o <<= 1) {
        int t = __shfl_up_sync(0xffffffffu, s, o);
        if (lane >= o) s += t;
    }
    if (lane == 31) wpre[wid] = s;
    __syncthreads();
    if (wid == 0) {
        int t = wpre[lane];
        #pragma unroll
        for (int o = 1; o < 32; o <<= 1) {
            int u = __shfl_up_sync(0xffffffffu, t, o);
            if (lane >= o) t += u;
        }
        wpre[lane] = t;
    }
    __syncthreads();
    int excl = s - v + (wid > 0 ? wpre[wid - 1] : 0) + g_bsum[blockIdx.x];
    if (i < N_NODES) { g_off[i] = excl; g_cur[i] = excl; }
}

// ---------------- CSR fill ----------------
__global__ void k_fill(const int* __restrict__ ei) {
    for (int e = blockIdx.x * blockDim.x + threadIdx.x; e < N_EDGESC;
         e += gridDim.x * blockDim.x) {
        int src = ei[e];
        int dst = ei[N_EDGESC + e];
        src = min(max(src, 0), N_NODES - 1);
        dst = min(max(dst, 0), N_NODES - 1);
        int pos = atomicAdd(&g_cur[dst], 1);
        g_es[pos] = src;
    }
}

// ================= GEMM1: BM=128 BN=128 BK=32, 3-stage, 2-term MMA =================
// N-fastest 1D grid: m = bx>>2, n = bx&3  -> 4 N-siblings co-resident, A rows
// hit DRAM once and L2 3x (A working set ~38MB << L2).
#define LDA1 40
#define LDB1 136
#define LDC1 136
#define S1_OFF_AL 10240
#define S1_OFF_BH 20480
#define STG1 29184
#define DYN1 (3 * STG1)
#define G1_MBLK ((N_NODES + 127) / 128)   // 782

__device__ __forceinline__ void g1_issue(char* st, int tid, int i0, int n0, int kt,
                                         int rows_left) {
    const int k0 = kt * 32;
    const uint32_t ah = smem_u32(st);
    const uint32_t al = ah + S1_OFF_AL;
    const uint32_t bh = ah + S1_OFF_BH;
    #pragma unroll
    for (int p = 0; p < 2; p++) {
        int idx = tid + p * 256;
        int row = idx >> 2;
        int ch = idx & 3;
        int n = (row < rows_left) ? 16 : 0;
        const __half* s = g_xs + (size_t)(i0 + row) * 2048 + k0 + ch * 8;
        CP_A16(ah + row * (LDA1 * 2) + ch * 16, s, n);
        CP_A16(al + row * (LDA1 * 2) + ch * 16, s + 1024, n);
    }
    #pragma unroll
    for (int p = 0; p < 2; p++) {
        int idx = tid + p * 256;
        int row = idx >> 4;
        int ch = idx & 15;
        const __half* sh = g_w1h + (size_t)(k0 + row) * H1 + n0 + ch * 8;
        CP_A16(bh + row * (LDB1 * 2) + ch * 16, sh, 16);
    }
    CP_COMMIT();
}

__global__ __launch_bounds__(256) void k_gemm1(const float* __restrict__ b1) {
    extern __shared__ __align__(128) char dyn[];
    const int bx = blockIdx.x;
    const int i0 = (bx >> 2) * 128;
    const int n0 = (bx & 3) * 128;
    const int tid = threadIdx.x;
    const int wid = tid >> 5;
    const int warpM = wid & 3, warpN = wid >> 2;   // 4x2 warps, warp tile 32x64
    const int rows_left = N_NODES - i0;

    wmma::fragment<wmma::accumulator, 16, 16, 16, float> acc[2][4];
    #pragma unroll
    for (int m = 0; m < 2; m++)
        #pragma unroll
        for (int n = 0; n < 4; n++) wmma::fill_fragment(acc[m][n], 0.f);

    g1_issue(dyn, tid, i0, n0, 0, rows_left);
    g1_issue(dyn + STG1, tid, i0, n0, 1, rows_left);

    for (int kt = 0; kt < 32; kt++) {
        if (kt < 30) CP_WAIT1(); else CP_WAIT0();
        __syncthreads();
        if (kt + 2 < 32) g1_issue(dyn + ((kt + 2) % 3) * STG1, tid, i0, n0, kt + 2, rows_left);
        char* st = dyn + (kt % 3) * STG1;
        __half (*Ah)[LDA1] = reinterpret_cast<__half(*)[LDA1]>(st);
        __half (*Al)[LDA1] = reinterpret_cast<__half(*)[LDA1]>(st + S1_OFF_AL);
        __half (*Bh)[LDB1] = reinterpret_cast<__half(*)[LDB1]>(st + S1_OFF_BH);
        #pragma unroll
        for (int kk = 0; kk < 32; kk += 16) {
            wmma::fragment<wmma::matrix_a, 16, 16, 16, __half, wmma::row_major> afH[2], afL[2];
            #pragma unroll
            for (int m = 0; m < 2; m++) {
                wmma::load_matrix_sync(afH[m], &Ah[warpM * 32 + m * 16][kk], LDA1);
                wmma::load_matrix_sync(afL[m], &Al[warpM * 32 + m * 16][kk], LDA1);
            }
            #pragma unroll
            for (int n = 0; n < 4; n++) {
                wmma::fragment<wmma::matrix_b, 16, 16, 16, __half, wmma::row_major> bfH;
                wmma::load_matrix_sync(bfH, &Bh[kk][warpN * 64 + n * 16], LDB1);
                #pragma unroll
                for (int m = 0; m < 2; m++) {
                    wmma::mma_sync(acc[m][n], afL[m], bfH, acc[m][n]);
                    wmma::mma_sync(acc[m][n], afH[m], bfH, acc[m][n]);
                }
            }
        }
    }

    __syncthreads();
    float (*Cs)[LDC1] = reinterpret_cast<float(*)[LDC1]>(dyn);
    #pragma unroll
    for (int m = 0; m < 2; m++)
        #pragma unroll
        for (int n = 0; n < 4; n++)
            wmma::store_matrix_sync(&Cs[warpM * 32 + m * 16][warpN * 64 + n * 16],
                                    acc[m][n], LDC1, wmma::mem_row_major);
    __syncthreads();
    #pragma unroll
    for (int q = 0; q < 32; q++) {
        int idx = q * 256 + tid;
        int r = idx >> 6, c2 = (idx & 63) * 2;
        int gi = i0 + r;
        if (gi < N_NODES) {
            float2 v;
            v.x = fmaxf(Cs[r][c2] + __ldg(&b1[n0 + c2]), 0.f);
            v.y = fmaxf(Cs[r][c2 + 1] + __ldg(&b1[n0 + c2 + 1]), 0.f);
            __half2 hi, lo;
            split_h2(v, hi, lo);
            *reinterpret_cast<__half2*>(&g_hs[(size_t)gi * 1024 + n0 + c2]) = hi;
            *reinterpret_cast<__half2*>(&g_hs[(size_t)gi * 1024 + 512 + n0 + c2]) = lo;
        }
    }
}

// ================= GEMM2 (3-term, 2-stage): y = dinv*(h @ W23 + demo @ Wg[256:] + c2) =================
#define G_LDA 40
#define G_LDB 136
#define G_LDC 136
#define SZ_A (128 * G_LDA * 2)
#define SZ_B (32 * G_LDB * 2)
#define OFF_AL SZ_A
#define OFF_BH (2 * SZ_A)
#define OFF_BL (2 * SZ_A + SZ_B)
#define G_STAGE (2 * SZ_A + 2 * SZ_B)
#define G_DYN (2 * G_STAGE)

__device__ __forceinline__ void issue_tile(
    char* st, int tid,
    const __half* Asrc, size_t a_stride, int a_rows_left, int kcol, int kpad,
    const __half* Bh, const __half* Bl, int b_stride, int k0, int n0)
{
    const uint32_t ah = smem_u32(st);
    const uint32_t al = ah + OFF_AL;
    const uint32_t bh = ah + OFF_BH;
    const uint32_t bl = ah + OFF_BL;
    #pragma unroll
    for (int p = 0; p < 2; p++) {
        int idx = tid + p * 256;
        int row = idx >> 2;
        int ch = idx & 3;
        int n = (row < a_rows_left) ? 16 : 0;
        const __half* s = Asrc + (size_t)row * a_stride + kcol + ch * 8;
        CP_A16(ah + row * (G_LDA * 2) + ch * 16, s, n);
        CP_A16(al + row * (G_LDA * 2) + ch * 16, s + kpad, n);
    }
    #pragma unroll
    for (int p = 0; p < 2; p++) {
        int idx = tid + p * 256;
        int row = idx >> 4;
        int ch = idx & 15;
        const __half* sh = Bh + (size_t)(k0 + row) * b_stride + n0 + ch * 8;
        const __half* sl = Bl + (size_t)(k0 + row) * b_stride + n0 + ch * 8;
        CP_A16(bh + row * (G_LDB * 2) + ch * 16, sh, 16);
        CP_A16(bl + row * (G_LDB * 2) + ch * 16, sl, 16);
    }
    CP_COMMIT();
}

__device__ __forceinline__ void mma_tile(
    char* st, int warpM, int warpN,
    wmma::fragment<wmma::accumulator, 16, 16, 16, float> (*acc)[4])
{
    __half (*Ah)[G_LDA] = reinterpret_cast<__half(*)[G_LDA]>(st);
    __half (*Al)[G_LDA] = reinterpret_cast<__half(*)[G_LDA]>(st + OFF_AL);
    __half (*Bh)[G_LDB] = reinterpret_cast<__half(*)[G_LDB]>(st + OFF_BH);
    __half (*Bl)[G_LDB] = reinterpret_cast<__half(*)[G_LDB]>(st + OFF_BL);
    #pragma unroll
    for (int kk = 0; kk < 32; kk += 16) {
        wmma::fragment<wmma::matrix_a, 16, 16, 16, __half, wmma::row_major> afH[2], afL[2];
        #pragma unroll
        for (int m = 0; m < 2; m++) {
            wmma::load_matrix_sync(afH[m], &Ah[warpM * 32 + m * 16][kk], G_LDA);
            wmma::load_matrix_sync(afL[m], &Al[warpM * 32 + m * 16][kk], G_LDA);
        }
        #pragma unroll
        for (int n = 0; n < 4; n++) {
            wmma::fragment<wmma::matrix_b, 16, 16, 16, __half, wmma::row_major> bfH, bfL;
            wmma::load_matrix_sync(bfH, &Bh[kk][warpN * 64 + n * 16], G_LDB);
            wmma::load_matrix_sync(bfL, &Bl[kk][warpN * 64 + n * 16], G_LDB);
            #pragma unroll
            for (int m = 0; m < 2; m++) {
                wmma::mma_sync(acc[m][n], afH[m], bfL, acc[m][n]);
                wmma::mma_sync(acc[m][n], afL[m], bfH, acc[m][n]);
                wmma::mma_sync(acc[m][n], afH[m], bfH, acc[m][n]);
            }
        }
    }
}

__global__ __launch_bounds__(256) void k_gemm2(const float* __restrict__ x,
                                               const float* __restrict__ Wg) {
    extern __shared__ __align__(128) char dyn[];
    __shared__ float demoS[128][10];
    __shared__ float WgbS[10][DG];
    __shared__ float c2S[DG];

    const int i0 = blockIdx.x * 128;
    const int tid = threadIdx.x;
    const int wid = tid >> 5;
    const int warpM = wid & 3, warpN = wid >> 2;
    const int rows_left = N_NODES - i0;

    for (int idx = tid; idx < 128 * 10; idx += 256) {
        int r = idx / 10, t = idx % 10;
        int gi = i0 + r;
        demoS[r][t] = (gi < N_NODES) ? x[(size_t)gi * XDIM + SUBJ + t] : 0.f;
    }
    for (int idx = tid; idx < 10 * DG; idx += 256) {
        int t = idx >> 7, c = idx & 127;
        WgbS[t][c] = Wg[(H2 + t) * DG + c];
    }
    if (tid < DG) c2S[tid] = g_c2[tid];

    wmma::fragment<wmma::accumulator, 16, 16, 16, float> acc[2][4];
    #pragma unroll
    for (int m = 0; m < 2; m++)
        #pragma unroll
        for (int n = 0; n < 4; n++) wmma::fill_fragment(acc[m][n], 0.f);

    issue_tile(dyn, tid, g_hs + (size_t)i0 * 1024, 1024, rows_left, 0, 512,
               g_w23h, g_w23l, DG, 0, 0);

    for (int kt = 0; kt < 16; kt++) {
        const int s = kt & 1;
        CP_WAIT0();
        __syncthreads();
        if (kt + 1 < 16)
            issue_tile(dyn + (s ^ 1) * G_STAGE, tid,
                       g_hs + (size_t)i0 * 1024, 1024, rows_left, (kt + 1) * 32, 512,
                       g_w23h, g_w23l, DG, (kt + 1) * 32, 0);
        mma_tile(dyn + s * G_STAGE, warpM, warpN, acc);
        __syncthreads();
    }

    float (*Cs)[G_LDC] = reinterpret_cast<float(*)[G_LDC]>(dyn);
    #pragma unroll
    for (int m = 0; m < 2; m++)
        #pragma unroll
        for (int n = 0; n < 4; n++)
            wmma::store_matrix_sync(&Cs[warpM * 32 + m * 16][warpN * 64 + n * 16],
                                    acc[m][n], G_LDC, wmma::mem_row_major);
    __syncthreads();
    #pragma unroll
    for (int q = 0; q < 64; q++) {
        int idx = q * 256 + tid;
        int r = idx >> 7, c = idx & 127;
        int gi = i0 + r;
        if (gi < N_NODES) {
            float v = Cs[r][c] + c2S[c];
            #pragma unroll
            for (int t = 0; t < 10; t++) v += demoS[r][t] * WgbS[t][c];
            float dinv = rsqrtf((float)g_deg[gi]);
            g_y[(size_t)gi * DG + c] = dinv * v;
        }
    }
}

// ---------------- gather + fused epilogue ----------------
__global__ __launch_bounds__(256) void k_gather(const float* __restrict__ bg,
                                                const float* __restrict__ Wo) {
    int wid = threadIdx.x >> 5, lane = threadIdx.x & 31;
    int node = blockIdx.x * 8 + wid;
    float dot = 0.f;
    if (node < N_NODES) {
        int deg = g_deg[node];
        int beg = g_off[node];
        int cnt = deg - 1;
        float4 a = *reinterpret_cast<const float4*>(&g_y[(size_t)node * DG + lane * 4]);
        #pragma unroll 4
        for (int j = 0; j < cnt; j++) {
            int s = __ldg(&g_es[beg + j]);
            float4 v = *reinterpret_cast<const float4*>(&g_y[(size_t)s * DG + lane * 4]);
            a.x += v.x; a.y += v.y; a.z += v.z; a.w += v.w;
        }
        float dinv = rsqrtf((float)deg);
        float4 bgv = *reinterpret_cast<const float4*>(&bg[lane * 4]);
        float4 wv = *reinterpret_cast<const float4*>(&Wo[lane * 4]);
        dot += fmaxf(dinv * a.x + bgv.x, 0.f) * wv.x;
        dot += fmaxf(dinv * a.y + bgv.y, 0.f) * wv.y;
        dot += fmaxf(dinv * a.z + bgv.z, 0.f) * wv.z;
        dot += fmaxf(dinv * a.w + bgv.w, 0.f) * wv.w;
    }
    #pragma unroll
    for (int o = 16; o; o >>= 1) dot += __shfl_down_sync(0xffffffffu, dot, o);
    __shared__ float part[8];
    if (lane == 0) part[wid] = dot;
    __syncthreads();
    if (threadIdx.x == 0) {
        float s = 0.f;
        #pragma unroll
        for (int w = 0; w < 8; w++) s += part[w];
        atomicAdd(&g_acc, (double)s);
    }
}

__global__ void k_fin(const float* __restrict__ bo, float* __restrict__ out) {
    out[0] = (float)(g_acc * (1.0 / (double)N_NODES) + (double)bo[0]);
}

// ---------------- launch ----------------
extern "C" void kernel_launch(void* const* d_in, const int* in_sizes, int n_in,
                              void* d_out, int out_size) {
    const float* x  = (const float*)d_in[0];
    const int*   ei = (const int*)d_in[1];
    const float* W1 = (const float*)d_in[2];
    const float* b1 = (const float*)d_in[3];
    const float* W2 = (const float*)d_in[4];
    const float* b2 = (const float*)d_in[5];
    const float* Wg = (const float*)d_in[6];
    const float* bg = (const float*)d_in[7];
    const float* Wo = (const float*)d_in[8];
    const float* bo = (const float*)d_in[9];
    float* out = (float*)d_out;

    cudaFuncSetAttribute(k_gemm1, cudaFuncAttributeMaxDynamicSharedMemorySize, DYN1);
    cudaFuncSetAttribute(k_gemm2, cudaFuncAttributeMaxDynamicSharedMemorySize, G_DYN);

    k_splitx<<<2048, 256>>>(x);                                   // 1
    k_splitw<<<(1024 * 256 + 255) / 256, 256>>>(W1);              // 2
    k_init<<<(N_NODES + 255) / 256, 256>>>();                     // 3
    k_gemm1<<<G1_MBLK * 4, 256, DYN1>>>(b1);                      // 4 <- ncu capture slot
    k_deg<<<4096, 256>>>(ei);                                     // 5
    k_scan1<<<SCAN_NBLK, SCAN_CHUNK>>>();                         // 6
    k_scan2<<<1, 128>>>();                                        // 7
    k_scan3<<<SCAN_NBLK, SCAN_CHUNK>>>();                         // 8
    k_fill<<<4096, 256>>>(ei);                                    // 9
    k_pre<<<H1 + 1, 128>>>(W2, Wg, b2);                           // 10
    k_gemm2<<<(N_NODES + 127) / 128, 256, G_DYN>>>(x, Wg);        // 11
    k_gather<<<(N_NODES + 7) / 8, 256>>>(bg, Wo);                 // 12
    k_fin<<<1, 1>>>(bo, out);                                     // 13
}

// round 10
// speedup vs baseline: 1.3211x; 1.3211x over previous
#include <cuda_runtime.h>
#include <cuda_fp16.h>
#include <mma.h>
#include <cstdint>

using namespace nvcuda;

#define N_NODES 100000
#define N_EDGESC 1600000
#define XDIM 1010
#define SUBJ 1000
#define H1 512
#define H2 256
#define DG 128

// ---------------- static device scratch ----------------
__device__ __half g_xs[(size_t)N_NODES * 1024];   // x hi only (K padded to 1024)
__device__ __half g_w1h[1024 * H1];               // W1 hi only (1-term GEMM1)
__device__ __half g_hs[(size_t)N_NODES * 1024];   // h split: [0..511]=hi, [512..1023]=lo
__device__ __half g_w23h[H1 * DG];
__device__ __half g_w23l[H1 * DG];
__device__ float  g_c2[DG];
__device__ float  g_y[(size_t)N_NODES * DG];
__device__ int    g_deg[N_NODES];
__device__ int    g_off[N_NODES];
__device__ int    g_cur[N_NODES];
__device__ int    g_es[N_EDGESC];
__device__ int    g_bsum[128];
__device__ double g_acc;

// ---------------- helpers ----------------
__device__ __forceinline__ uint32_t smem_u32(const void* p) {
    uint32_t a;
    asm("{ .reg .u64 t; cvta.to.shared.u64 t, %1; cvt.u32.u64 %0, t; }" : "=r"(a) : "l"(p));
    return a;
}
#define CP_A16(dst, src, n) \
    asm volatile("cp.async.cg.shared.global [%0], [%1], 16, %2;" :: "r"(dst), "l"(src), "r"(n))
#define CP_COMMIT() asm volatile("cp.async.commit_group;" ::: "memory")
#define CP_WAIT0()  asm volatile("cp.async.wait_group 0;" ::: "memory")
#define CP_WAIT1()  asm volatile("cp.async.wait_group 1;" ::: "memory")

__device__ __forceinline__ void split_h2(float2 v, __half2& hi, __half2& lo) {
    hi = __float22half2_rn(v);
    float2 l = make_float2(v.x - __half2float(__low2half(hi)),
                           v.y - __half2float(__high2half(hi)));
    lo = __float22half2_rn(l);
}

// ---------------- x -> fp16 hi ----------------
__global__ void k_splitx(const float* __restrict__ x) {
    for (long long id = (long long)blockIdx.x * blockDim.x + threadIdx.x;
         id < (long long)N_NODES * 512; id += (long long)gridDim.x * blockDim.x) {
        int row = (int)(id >> 9);
        int col = (int)(id & 511) * 2;
        float2 v = make_float2(0.f, 0.f);
        if (col < SUBJ) v = *reinterpret_cast<const float2*>(&x[(size_t)row * XDIM + col]);
        *reinterpret_cast<__half2*>(&g_xs[(size_t)row * 1024 + col]) = __float22half2_rn(v);
    }
}

// ---------------- W1 -> fp16 hi ----------------
__global__ void k_splitw(const float* __restrict__ W1) {
    int id = blockIdx.x * blockDim.x + threadIdx.x;
    if (id >= 1024 * 256) return;
    int row = id >> 8;
    int col = (id & 255) * 2;
    float2 v = make_float2(0.f, 0.f);
    if (row < SUBJ) v = *reinterpret_cast<const float2*>(&W1[(size_t)row * H1 + col]);
    *reinterpret_cast<__half2*>(&g_w1h[row * H1 + col]) = __float22half2_rn(v);
}

// ---------------- init ----------------
__global__ void k_init() {
    int i = blockIdx.x * blockDim.x + threadIdx.x;
    if (i < N_NODES) g_deg[i] = 1;
    if (i == 0) g_acc = 0.0;
}

// ---------------- weight fold (split fp16) ----------------
__global__ void k_pre(const float* __restrict__ W2, const float* __restrict__ Wg,
                      const float* __restrict__ b2) {
    int k = blockIdx.x;
    int j = threadIdx.x;
    if (k < H1) {
        __shared__ float row[H2];
        for (int m = j; m < H2; m += 128) row[m] = W2[k * H2 + m];
        __syncthreads();
        float acc = 0.f;
        #pragma unroll 4
        for (int m = 0; m < H2; m++) acc += row[m] * Wg[m * DG + j];
        __half h = __float2half_rn(acc);
        g_w23h[k * DG + j] = h;
        g_w23l[k * DG + j] = __float2half_rn(acc - __half2float(h));
    } else {
        float acc = 0.f;
        for (int m = 0; m < H2; m++) acc += b2[m] * Wg[m * DG + j];
        g_c2[j] = acc;
    }
}

// ---------------- degree count ----------------
__global__ void k_deg(const int* __restrict__ ei) {
    for (int e = blockIdx.x * blockDim.x + threadIdx.x; e < N_EDGESC;
         e += gridDim.x * blockDim.x) {
        int dst = ei[N_EDGESC + e];
        dst = min(max(dst, 0), N_NODES - 1);
        atomicAdd(&g_deg[dst], 1);
    }
}

// ---------------- multi-block scan ----------------
#define SCAN_CHUNK 1024
#define SCAN_NBLK ((N_NODES + SCAN_CHUNK - 1) / SCAN_CHUNK)  // 98

__global__ void k_scan1() {
    __shared__ int wsum[32];
    int i = blockIdx.x * SCAN_CHUNK + threadIdx.x;
    int v = (i < N_NODES) ? (g_deg[i] - 1) : 0;
    #pragma unroll
    for (int o = 16; o; o >>= 1) v += __shfl_down_sync(0xffffffffu, v, o);
    int lane = threadIdx.x & 31, wid = threadIdx.x >> 5;
    if (lane == 0) wsum[wid] = v;
    __syncthreads();
    if (wid == 0) {
        int t = wsum[lane];
        #pragma unroll
        for (int o = 16; o; o >>= 1) t += __shfl_down_sync(0xffffffffu, t, o);
        if (lane == 0) g_bsum[blockIdx.x] = t;
    }
}

__global__ void k_scan2() {
    __shared__ int wtot[4];
    int tid = threadIdx.x, lane = tid & 31, wid = tid >> 5;
    int v = (tid < SCAN_NBLK) ? g_bsum[tid] : 0;
    int s = v;
    #pragma unroll
    for (int o = 1; o < 32; o <<= 1) {
        int t = __shfl_up_sync(0xffffffffu, s, o);
        if (lane >= o) s += t;
    }
    if (lane == 31) wtot[wid] = s;
    __syncthreads();
    int base = 0;
    for (int w = 0; w < wid; w++) base += wtot[w];
    if (tid < SCAN_NBLK) g_bsum[tid] = base + s - v;
}

__global__ void k_scan3() {
    __shared__ int wpre[32];
    int tid = threadIdx.x, lane = tid & 31, wid = tid >> 5;
    int i = blockIdx.x * SCAN_CHUNK + tid;
    int v = (i < N_NODES) ? (g_deg[i] - 1) : 0;
    int s = v;
    #pragma unroll
    for (int o = 1; o < 32; o <<= 1) {
        int t = __shfl_up_sync(0xffffffffu, s, o);
        if (lane >= o) s += t;
    }
    if (lane == 31) wpre[wid] = s;
    __syncthreads();
    if (wid == 0) {
        int t = wpre[lane];
        #pragma unroll
        for (int o = 1; o < 32; o <<= 1) {
            int u = __shfl_up_sync(0xffffffffu, t, o);
            if (lane >= o) t += u;
        }
        wpre[lane] = t;
    }
    __syncthreads();
    int excl = s - v + (wid > 0 ? wpre[wid - 1] : 0) + g_bsum[blockIdx.x];
    if (i < N_NODES) { g_off[i] = excl; g_cur[i] = excl; }
}

// ---------------- CSR fill ----------------
__global__ void k_fill(const int* __restrict__ ei) {
    for (int e = blockIdx.x * blockDim.x + threadIdx.x; e < N_EDGESC;
         e += gridDim.x * blockDim.x) {
        int src = ei[e];
        int dst = ei[N_EDGESC + e];
        src = min(max(src, 0), N_NODES - 1);
        dst = min(max(dst, 0), N_NODES - 1);
        int pos = atomicAdd(&g_cur[dst], 1);
        g_es[pos] = src;
    }
}

// ================= GEMM1: BM=128 BN=128 BK=32, 3-stage, 1-term fp16 =================
// N-fastest 1D grid: m = bx>>2, n = bx&3 (A rows DRAM once, L2 3x).
// stage: AH[128x40] 10240 | BH[32x136] 8704 => 18944; pipeline 3x = 56832.
// DYN1 must ALSO cover the fp32 epilogue buffer 128*136*4 = 69632 (> 56832).
#define LDA1 40
#define LDB1 136
#define LDC1 136
#define S1_OFF_BH 10240
#define STG1 18944
#define DYN1 69632
#define G1_MBLK ((N_NODES + 127) / 128)   // 782

__device__ __forceinline__ void g1_issue(char* st, int tid, int i0, int n0, int kt,
                                         int rows_left) {
    const int k0 = kt * 32;
    const uint32_t ah = smem_u32(st);
    const uint32_t bh = ah + S1_OFF_BH;
    // A hi: 128 rows x 4 chunks of 16B
    #pragma unroll
    for (int p = 0; p < 2; p++) {
        int idx = tid + p * 256;
        int row = idx >> 2;
        int ch = idx & 3;
        int n = (row < rows_left) ? 16 : 0;
        const __half* s = g_xs + (size_t)(i0 + row) * 1024 + k0 + ch * 8;
        CP_A16(ah + row * (LDA1 * 2) + ch * 16, s, n);
    }
    // B hi: 32 rows x 16 chunks of 16B
    #pragma unroll
    for (int p = 0; p < 2; p++) {
        int idx = tid + p * 256;
        int row = idx >> 4;
        int ch = idx & 15;
        const __half* sh = g_w1h + (size_t)(k0 + row) * H1 + n0 + ch * 8;
        CP_A16(bh + row * (LDB1 * 2) + ch * 16, sh, 16);
    }
    CP_COMMIT();
}

__global__ __launch_bounds__(256) void k_gemm1(const float* __restrict__ b1) {
    extern __shared__ __align__(128) char dyn[];
    const int bx = blockIdx.x;
    const int i0 = (bx >> 2) * 128;
    const int n0 = (bx & 3) * 128;
    const int tid = threadIdx.x;
    const int wid = tid >> 5;
    const int warpM = wid & 3, warpN = wid >> 2;   // 4x2 warps, warp tile 32x64
    const int rows_left = N_NODES - i0;

    wmma::fragment<wmma::accumulator, 16, 16, 16, float> acc[2][4];
    #pragma unroll
    for (int m = 0; m < 2; m++)
        #pragma unroll
        for (int n = 0; n < 4; n++) wmma::fill_fragment(acc[m][n], 0.f);

    g1_issue(dyn, tid, i0, n0, 0, rows_left);
    g1_issue(dyn + STG1, tid, i0, n0, 1, rows_left);

    for (int kt = 0; kt < 32; kt++) {
        if (kt < 30) CP_WAIT1(); else CP_WAIT0();
        __syncthreads();
        if (kt + 2 < 32) g1_issue(dyn + ((kt + 2) % 3) * STG1, tid, i0, n0, kt + 2, rows_left);
        char* st = dyn + (kt % 3) * STG1;
        __half (*Ah)[LDA1] = reinterpret_cast<__half(*)[LDA1]>(st);
        __half (*Bh)[LDB1] = reinterpret_cast<__half(*)[LDB1]>(st + S1_OFF_BH);
        #pragma unroll
        for (int kk = 0; kk < 32; kk += 16) {
            wmma::fragment<wmma::matrix_a, 16, 16, 16, __half, wmma::row_major> afH[2];
            #pragma unroll
            for (int m = 0; m < 2; m++)
                wmma::load_matrix_sync(afH[m], &Ah[warpM * 32 + m * 16][kk], LDA1);
            #pragma unroll
            for (int n = 0; n < 4; n++) {
                wmma::fragment<wmma::matrix_b, 16, 16, 16, __half, wmma::row_major> bfH;
                wmma::load_matrix_sync(bfH, &Bh[kk][warpN * 64 + n * 16], LDB1);
                #pragma unroll
                for (int m = 0; m < 2; m++)
                    wmma::mma_sync(acc[m][n], afH[m], bfH, acc[m][n]);
            }
        }
    }

    __syncthreads();
    float (*Cs)[LDC1] = reinterpret_cast<float(*)[LDC1]>(dyn);
    #pragma unroll
    for (int m = 0; m < 2; m++)
        #pragma unroll
        for (int n = 0; n < 4; n++)
            wmma::store_matrix_sync(&Cs[warpM * 32 + m * 16][warpN * 64 + n * 16],
                                    acc[m][n], LDC1, wmma::mem_row_major);
    __syncthreads();
    #pragma unroll
    for (int q = 0; q < 32; q++) {
        int idx = q * 256 + tid;
        int r = idx >> 6, c2 = (idx & 63) * 2;
        int gi = i0 + r;
        if (gi < N_NODES) {
            float2 v;
            v.x = fmaxf(Cs[r][c2] + __ldg(&b1[n0 + c2]), 0.f);
            v.y = fmaxf(Cs[r][c2 + 1] + __ldg(&b1[n0 + c2 + 1]), 0.f);
            __half2 hi, lo;
            split_h2(v, hi, lo);
            *reinterpret_cast<__half2*>(&g_hs[(size_t)gi * 1024 + n0 + c2]) = hi;
            *reinterpret_cast<__half2*>(&g_hs[(size_t)gi * 1024 + 512 + n0 + c2]) = lo;
        }
    }
}

// ================= GEMM2 (3-term, 2-stage): y = dinv*(h @ W23 + demo @ Wg[256:] + c2) =================
#define G_LDA 40
#define G_LDB 136
#define G_LDC 136
#define SZ_A (128 * G_LDA * 2)
#define SZ_B (32 * G_LDB * 2)
#define OFF_AL SZ_A
#define OFF_BH (2 * SZ_A)
#define OFF_BL (2 * SZ_A + SZ_B)
#define G_STAGE (2 * SZ_A + 2 * SZ_B)
#define G_DYN (2 * G_STAGE)

__device__ __forceinline__ void issue_tile(
    char* st, int tid,
    const __half* Asrc, size_t a_stride, int a_rows_left, int kcol, int kpad,
    const __half* Bh, const __half* Bl, int b_stride, int k0, int n0)
{
    const uint32_t ah = smem_u32(st);
    const uint32_t al = ah + OFF_AL;
    const uint32_t bh = ah + OFF_BH;
    const uint32_t bl = ah + OFF_BL;
    #pragma unroll
    for (int p = 0; p < 2; p++) {
        int idx = tid + p * 256;
        int row = idx >> 2;
        int ch = idx & 3;
        int n = (row < a_rows_left) ? 16 : 0;
        const __half* s = Asrc + (size_t)row * a_stride + kcol + ch * 8;
        CP_A16(ah + row * (G_LDA * 2) + ch * 16, s, n);
        CP_A16(al + row * (G_LDA * 2) + ch * 16, s + kpad, n);
    }
    #pragma unroll
    for (int p = 0; p < 2; p++) {
        int idx = tid + p * 256;
        int row = idx >> 4;
        int ch = idx & 15;
        const __half* sh = Bh + (size_t)(k0 + row) * b_stride + n0 + ch * 8;
        const __half* sl = Bl + (size_t)(k0 + row) * b_stride + n0 + ch * 8;
        CP_A16(bh + row * (G_LDB * 2) + ch * 16, sh, 16);
        CP_A16(bl + row * (G_LDB * 2) + ch * 16, sl, 16);
    }
    CP_COMMIT();
}

__device__ __forceinline__ void mma_tile(
    char* st, int warpM, int warpN,
    wmma::fragment<wmma::accumulator, 16, 16, 16, float> (*acc)[4])
{
    __half (*Ah)[G_LDA] = reinterpret_cast<__half(*)[G_LDA]>(st);
    __half (*Al)[G_LDA] = reinterpret_cast<__half(*)[G_LDA]>(st + OFF_AL);
    __half (*Bh)[G_LDB] = reinterpret_cast<__half(*)[G_LDB]>(st + OFF_BH);
    __half (*Bl)[G_LDB] = reinterpret_cast<__half(*)[G_LDB]>(st + OFF_BL);
    #pragma unroll
    for (int kk = 0; kk < 32; kk += 16) {
        wmma::fragment<wmma::matrix_a, 16, 16, 16, __half, wmma::row_major> afH[2], afL[2];
        #pragma unroll
        for (int m = 0; m < 2; m++) {
            wmma::load_matrix_sync(afH[m], &Ah[warpM * 32 + m * 16][kk], G_LDA);
            wmma::load_matrix_sync(afL[m], &Al[warpM * 32 + m * 16][kk], G_LDA);
        }
        #pragma unroll
        for (int n = 0; n < 4; n++) {
            wmma::fragment<wmma::matrix_b, 16, 16, 16, __half, wmma::row_major> bfH, bfL;
            wmma::load_matrix_sync(bfH, &Bh[kk][warpN * 64 + n * 16], G_LDB);
            wmma::load_matrix_sync(bfL, &Bl[kk][warpN * 64 + n * 16], G_LDB);
            #pragma unroll
            for (int m = 0; m < 2; m++) {
                wmma::mma_sync(acc[m][n], afH[m], bfL, acc[m][n]);
                wmma::mma_sync(acc[m][n], afL[m], bfH, acc[m][n]);
                wmma::mma_sync(acc[m][n], afH[m], bfH, acc[m][n]);
            }
        }
    }
}

__global__ __launch_bounds__(256) void k_gemm2(const float* __restrict__ x,
                                               const float* __restrict__ Wg) {
    extern __shared__ __align__(128) char dyn[];
    __shared__ float demoS[128][10];
    __shared__ float WgbS[10][DG];
    __shared__ float c2S[DG];

    const int i0 = blockIdx.x * 128;
    const int tid = threadIdx.x;
    const int wid = tid >> 5;
    const int warpM = wid & 3, warpN = wid >> 2;
    const int rows_left = N_NODES - i0;

    for (int idx = tid; idx < 128 * 10; idx += 256) {
        int r = idx / 10, t = idx % 10;
        int gi = i0 + r;
        demoS[r][t] = (gi < N_NODES) ? x[(size_t)gi * XDIM + SUBJ + t] : 0.f;
    }
    for (int idx = tid; idx < 10 * DG; idx += 256) {
        int t = idx >> 7, c = idx & 127;
        WgbS[t][c] = Wg[(H2 + t) * DG + c];
    }
    if (tid < DG) c2S[tid] = g_c2[tid];

    wmma::fragment<wmma::accumulator, 16, 16, 16, float> acc[2][4];
    #pragma unroll
    for (int m = 0; m < 2; m++)
        #pragma unroll
        for (int n = 0; n < 4; n++) wmma::fill_fragment(acc[m][n], 0.f);

    issue_tile(dyn, tid, g_hs + (size_t)i0 * 1024, 1024, rows_left, 0, 512,
               g_w23h, g_w23l, DG, 0, 0);

    for (int kt = 0; kt < 16; kt++) {
        const int s = kt & 1;
        CP_WAIT0();
        __syncthreads();
        if (kt + 1 < 16)
            issue_tile(dyn + (s ^ 1) * G_STAGE, tid,
                       g_hs + (size_t)i0 * 1024, 1024, rows_left, (kt + 1) * 32, 512,
                       g_w23h, g_w23l, DG, (kt + 1) * 32, 0);
        mma_tile(dyn + s * G_STAGE, warpM, warpN, acc);
        __syncthreads();
    }

    float (*Cs)[G_LDC] = reinterpret_cast<float(*)[G_LDC]>(dyn);
    #pragma unroll
    for (int m = 0; m < 2; m++)
        #pragma unroll
        for (int n = 0; n < 4; n++)
            wmma::store_matrix_sync(&Cs[warpM * 32 + m * 16][warpN * 64 + n * 16],
                                    acc[m][n], G_LDC, wmma::mem_row_major);
    __syncthreads();
    #pragma unroll
    for (int q = 0; q < 64; q++) {
        int idx = q * 256 + tid;
        int r = idx >> 7, c = idx & 127;
        int gi = i0 + r;
        if (gi < N_NODES) {
            float v = Cs[r][c] + c2S[c];
            #pragma unroll
            for (int t = 0; t < 10; t++) v += demoS[r][t] * WgbS[t][c];
            float dinv = rsqrtf((float)g_deg[gi]);
            g_y[(size_t)gi * DG + c] = dinv * v;
        }
    }
}

// ---------------- gather + fused epilogue ----------------
__global__ __launch_bounds__(256) void k_gather(const float* __restrict__ bg,
                                                const float* __restrict__ Wo) {
    int wid = threadIdx.x >> 5, lane = threadIdx.x & 31;
    int node = blockIdx.x * 8 + wid;
    float dot = 0.f;
    if (node < N_NODES) {
        int deg = g_deg[node];
        int beg = g_off[node];
        int cnt = deg - 1;
        float4 a = *reinterpret_cast<const float4*>(&g_y[(size_t)node * DG + lane * 4]);
        #pragma unroll 4
        for (int j = 0; j < cnt; j++) {
            int s = __ldg(&g_es[beg + j]);
            float4 v = *reinterpret_cast<const float4*>(&g_y[(size_t)s * DG + lane * 4]);
            a.x += v.x; a.y += v.y; a.z += v.z; a.w += v.w;
        }
        float dinv = rsqrtf((float)deg);
        float4 bgv = *reinterpret_cast<const float4*>(&bg[lane * 4]);
        float4 wv = *reinterpret_cast<const float4*>(&Wo[lane * 4]);
        dot += fmaxf(dinv * a.x + bgv.x, 0.f) * wv.x;
        dot += fmaxf(dinv * a.y + bgv.y, 0.f) * wv.y;
        dot += fmaxf(dinv * a.z + bgv.z, 0.f) * wv.z;
        dot += fmaxf(dinv * a.w + bgv.w, 0.f) * wv.w;
    }
    #pragma unroll
    for (int o = 16; o; o >>= 1) dot += __shfl_down_sync(0xffffffffu, dot, o);
    __shared__ float part[8];
    if (lane == 0) part[wid] = dot;
    __syncthreads();
    if (threadIdx.x == 0) {
        float s = 0.f;
        #pragma unroll
        for (int w = 0; w < 8; w++) s += part[w];
        atomicAdd(&g_acc, (double)s);
    }
}

__global__ void k_fin(const float* __restrict__ bo, float* __restrict__ out) {
    out[0] = (float)(g_acc * (1.0 / (double)N_NODES) + (double)bo[0]);
}

// ---------------- launch ----------------
extern "C" void kernel_launch(void* const* d_in, const int* in_sizes, int n_in,
                              void* d_out, int out_size) {
    const float* x  = (const float*)d_in[0];
    const int*   ei = (const int*)d_in[1];
    const float* W1 = (const float*)d_in[2];
    const float* b1 = (const float*)d_in[3];
    const float* W2 = (const float*)d_in[4];
    const float* b2 = (const float*)d_in[5];
    const float* Wg = (const float*)d_in[6];
    const float* bg = (const float*)d_in[7];
    const float* Wo = (const float*)d_in[8];
    const float* bo = (const float*)d_in[9];
    float* out = (float*)d_out;

    cudaFuncSetAttribute(k_gemm1, cudaFuncAttributeMaxDynamicSharedMemorySize, DYN1);
    cudaFuncSetAttribute(k_gemm2, cudaFuncAttributeMaxDynamicSharedMemorySize, G_DYN);

    k_splitx<<<2048, 256>>>(x);                                   // 1
    k_splitw<<<(1024 * 256 + 255) / 256, 256>>>(W1);              // 2
    k_init<<<(N_NODES + 255) / 256, 256>>>();                     // 3
    k_gemm1<<<G1_MBLK * 4, 256, DYN1>>>(b1);                      // 4 <- ncu capture slot
    k_deg<<<4096, 256>>>(ei);                                     // 5
    k_scan1<<<SCAN_NBLK, SCAN_CHUNK>>>();                         // 6
    k_scan2<<<1, 128>>>();                                        // 7
    k_scan3<<<SCAN_NBLK, SCAN_CHUNK>>>();                         // 8
    k_fill<<<4096, 256>>>(ei);                                    // 9
    k_pre<<<H1 + 1, 128>>>(W2, Wg, b2);                           // 10
    k_gemm2<<<(N_NODES + 127) / 128, 256, G_DYN>>>(x, Wg);        // 11
    k_gather<<<(N_NODES + 7) / 8, 256>>>(bg, Wo);                 // 12
    k_fin<<<1, 1>>>(bo, out);                                     // 13
}

// round 11
// speedup vs baseline: 1.4539x; 1.1005x over previous
#include <cuda_runtime.h>
#include <cuda_fp16.h>
#include <mma.h>
#include <cstdint>

using namespace nvcuda;

#define N_NODES 100000
#define N_EDGESC 1600000
#define XDIM 1010
#define SUBJ 1000
#define H1 512
#define H2 256
#define DG 128

// ---------------- static device scratch ----------------
__device__ __half g_xs[(size_t)N_NODES * 1024];   // x hi (K padded to 1024)
__device__ __half g_w1h[1024 * H1];               // W1 hi
__device__ __half g_hs[(size_t)N_NODES * 512];    // h hi only
__device__ __half g_w23h[H1 * DG];                // folded W2@Wg hi only
__device__ float  g_c2[DG];
__device__ float  g_y[(size_t)N_NODES * DG];
__device__ int    g_deg[N_NODES];
__device__ int    g_off[N_NODES];
__device__ int    g_cur[N_NODES];
__device__ int    g_es[N_EDGESC];
__device__ int    g_bsum[128];
__device__ double g_acc;

// ---------------- helpers ----------------
__device__ __forceinline__ uint32_t smem_u32(const void* p) {
    uint32_t a;
    asm("{ .reg .u64 t; cvta.to.shared.u64 t, %1; cvt.u32.u64 %0, t; }" : "=r"(a) : "l"(p));
    return a;
}
#define CP_A16(dst, src, n) \
    asm volatile("cp.async.cg.shared.global [%0], [%1], 16, %2;" :: "r"(dst), "l"(src), "r"(n))
#define CP_COMMIT() asm volatile("cp.async.commit_group;" ::: "memory")
#define CP_WAIT0()  asm volatile("cp.async.wait_group 0;" ::: "memory")
#define CP_WAIT1()  asm volatile("cp.async.wait_group 1;" ::: "memory")

// ---------------- x -> fp16 hi ----------------
__global__ void k_splitx(const float* __restrict__ x) {
    for (long long id = (long long)blockIdx.x * blockDim.x + threadIdx.x;
         id < (long long)N_NODES * 512; id += (long long)gridDim.x * blockDim.x) {
        int row = (int)(id >> 9);
        int col = (int)(id & 511) * 2;
        float2 v = make_float2(0.f, 0.f);
        if (col < SUBJ) v = *reinterpret_cast<const float2*>(&x[(size_t)row * XDIM + col]);
        *reinterpret_cast<__half2*>(&g_xs[(size_t)row * 1024 + col]) = __float22half2_rn(v);
    }
}

// ---------------- W1 -> fp16 hi ----------------
__global__ void k_splitw(const float* __restrict__ W1) {
    int id = blockIdx.x * blockDim.x + threadIdx.x;
    if (id >= 1024 * 256) return;
    int row = id >> 8;
    int col = (id & 255) * 2;
    float2 v = make_float2(0.f, 0.f);
    if (row < SUBJ) v = *reinterpret_cast<const float2*>(&W1[(size_t)row * H1 + col]);
    *reinterpret_cast<__half2*>(&g_w1h[row * H1 + col]) = __float22half2_rn(v);
}

// ---------------- init ----------------
__global__ void k_init() {
    int i = blockIdx.x * blockDim.x + threadIdx.x;
    if (i < N_NODES) g_deg[i] = 1;
    if (i == 0) g_acc = 0.0;
}

// ---------------- weight fold (fp16 hi) ----------------
__global__ void k_pre(const float* __restrict__ W2, const float* __restrict__ Wg,
                      const float* __restrict__ b2) {
    int k = blockIdx.x;
    int j = threadIdx.x;
    if (k < H1) {
        __shared__ float row[H2];
        for (int m = j; m < H2; m += 128) row[m] = W2[k * H2 + m];
        __syncthreads();
        float acc = 0.f;
        #pragma unroll 4
        for (int m = 0; m < H2; m++) acc += row[m] * Wg[m * DG + j];
        g_w23h[k * DG + j] = __float2half_rn(acc);
    } else {
        float acc = 0.f;
        for (int m = 0; m < H2; m++) acc += b2[m] * Wg[m * DG + j];
        g_c2[j] = acc;
    }
}

// ---------------- degree count ----------------
__global__ void k_deg(const int* __restrict__ ei) {
    for (int e = blockIdx.x * blockDim.x + threadIdx.x; e < N_EDGESC;
         e += gridDim.x * blockDim.x) {
        int dst = ei[N_EDGESC + e];
        dst = min(max(dst, 0), N_NODES - 1);
        atomicAdd(&g_deg[dst], 1);
    }
}

// ---------------- multi-block scan ----------------
#define SCAN_CHUNK 1024
#define SCAN_NBLK ((N_NODES + SCAN_CHUNK - 1) / SCAN_CHUNK)  // 98

__global__ void k_scan1() {
    __shared__ int wsum[32];
    int i = blockIdx.x * SCAN_CHUNK + threadIdx.x;
    int v = (i < N_NODES) ? (g_deg[i] - 1) : 0;
    #pragma unroll
    for (int o = 16; o; o >>= 1) v += __shfl_down_sync(0xffffffffu, v, o);
    int lane = threadIdx.x & 31, wid = threadIdx.x >> 5;
    if (lane == 0) wsum[wid] = v;
    __syncthreads();
    if (wid == 0) {
        int t = wsum[lane];
        #pragma unroll
        for (int o = 16; o; o >>= 1) t += __shfl_down_sync(0xffffffffu, t, o);
        if (lane == 0) g_bsum[blockIdx.x] = t;
    }
}

__global__ void k_scan2() {
    __shared__ int wtot[4];
    int tid = threadIdx.x, lane = tid & 31, wid = tid >> 5;
    int v = (tid < SCAN_NBLK) ? g_bsum[tid] : 0;
    int s = v;
    #pragma unroll
    for (int o = 1; o < 32; o <<= 1) {
        int t = __shfl_up_sync(0xffffffffu, s, o);
        if (lane >= o) s += t;
    }
    if (lane == 31) wtot[wid] = s;
    __syncthreads();
    int base = 0;
    for (int w = 0; w < wid; w++) base += wtot[w];
    if (tid < SCAN_NBLK) g_bsum[tid] = base + s - v;
}

__global__ void k_scan3() {
    __shared__ int wpre[32];
    int tid = threadIdx.x, lane = tid & 31, wid = tid >> 5;
    int i = blockIdx.x * SCAN_CHUNK + tid;
    int v = (i < N_NODES) ? (g_deg[i] - 1) : 0;
    int s = v;
    #pragma unroll
    for (int o = 1; o < 32; o <<= 1) {
        int t = __shfl_up_sync(0xffffffffu, s, o);
        if (lane >= o) s += t;
    }
    if (lane == 31) wpre[wid] = s;
    __syncthreads();
    if (wid == 0) {
        int t = wpre[lane];
        #pragma unroll
        for (int o = 1; o < 32; o <<= 1) {
            int u = __shfl_up_sync(0xffffffffu, t, o);
            if (lane >= o) t += u;
        }
        wpre[lane] = t;
    }
    __syncthreads();
    int excl = s - v + (wid > 0 ? wpre[wid - 1] : 0) + g_bsum[blockIdx.x];
    if (i < N_NODES) { g_off[i] = excl; g_cur[i] = excl; }
}

// ---------------- CSR fill ----------------
__global__ void k_fill(const int* __restrict__ ei) {
    for (int e = blockIdx.x * blockDim.x + threadIdx.x; e < N_EDGESC;
         e += gridDim.x * blockDim.x) {
        int src = ei[e];
        int dst = ei[N_EDGESC + e];
        src = min(max(src, 0), N_NODES - 1);
        dst = min(max(dst, 0), N_NODES - 1);
        int pos = atomicAdd(&g_cur[dst], 1);
        g_es[pos] = src;
    }
}

// ================= GEMM geometry (shared by gemm1/gemm2) =================
#define LDA1 40
#define LDB1 136
#define LDC1 136
#define S1_OFF_BH 10240
#define STG1 18944               // AH 10240 + BH 8704
#define DYN1 69632               // max(3*STG1=56832, epilogue 128*136*4=69632)
#define G1_MBLK ((N_NODES + 127) / 128)   // 782

// generic 1-term issue: A[128 x 32] from (Asrc, a_stride), B[32 x 128] from (Bsrc, b_stride)
__device__ __forceinline__ void g_issue(char* st, int tid, int kt, int rows_left,
                                        const __half* Asrc, int a_stride,
                                        const __half* Bsrc, int b_stride) {
    const int k0 = kt * 32;
    const uint32_t ah = smem_u32(st);
    const uint32_t bh = ah + S1_OFF_BH;
    #pragma unroll
    for (int p = 0; p < 2; p++) {
        int idx = tid + p * 256;
        int row = idx >> 2;
        int ch = idx & 3;
        int n = (row < rows_left) ? 16 : 0;
        const __half* s = Asrc + (size_t)row * a_stride + k0 + ch * 8;
        CP_A16(ah + row * (LDA1 * 2) + ch * 16, s, n);
    }
    #pragma unroll
    for (int p = 0; p < 2; p++) {
        int idx = tid + p * 256;
        int row = idx >> 4;
        int ch = idx & 15;
        const __half* sh = Bsrc + (size_t)(k0 + row) * b_stride + ch * 8;
        CP_A16(bh + row * (LDB1 * 2) + ch * 16, sh, 16);
    }
    CP_COMMIT();
}

// 1-term MMA over one 32-k tile
__device__ __forceinline__ void g_mma(char* st, int warpM, int warpN,
    wmma::fragment<wmma::accumulator, 16, 16, 16, float> (*acc)[4])
{
    __half (*Ah)[LDA1] = reinterpret_cast<__half(*)[LDA1]>(st);
    __half (*Bh)[LDB1] = reinterpret_cast<__half(*)[LDB1]>(st + S1_OFF_BH);
    #pragma unroll
    for (int kk = 0; kk < 32; kk += 16) {
        wmma::fragment<wmma::matrix_a, 16, 16, 16, __half, wmma::row_major> afH[2];
        #pragma unroll
        for (int m = 0; m < 2; m++)
            wmma::load_matrix_sync(afH[m], &Ah[warpM * 32 + m * 16][kk], LDA1);
        #pragma unroll
        for (int n = 0; n < 4; n++) {
            wmma::fragment<wmma::matrix_b, 16, 16, 16, __half, wmma::row_major> bfH;
            wmma::load_matrix_sync(bfH, &Bh[kk][warpN * 64 + n * 16], LDB1);
            #pragma unroll
            for (int m = 0; m < 2; m++)
                wmma::mma_sync(acc[m][n], afH[m], bfH, acc[m][n]);
        }
    }
}

// ================= GEMM1: h_hi = relu(x @ W1 + b1) =================
__global__ __launch_bounds__(256) void k_gemm1(const float* __restrict__ b1) {
    extern __shared__ __align__(128) char dyn[];
    const int bx = blockIdx.x;
    const int i0 = (bx >> 2) * 128;
    const int n0 = (bx & 3) * 128;
    const int tid = threadIdx.x;
    const int wid = tid >> 5;
    const int warpM = wid & 3, warpN = wid >> 2;
    const int rows_left = N_NODES - i0;
    const __half* Asrc = g_xs + (size_t)i0 * 1024;
    const __half* Bsrc = g_w1h + n0;

    wmma::fragment<wmma::accumulator, 16, 16, 16, float> acc[2][4];
    #pragma unroll
    for (int m = 0; m < 2; m++)
        #pragma unroll
        for (int n = 0; n < 4; n++) wmma::fill_fragment(acc[m][n], 0.f);

    g_issue(dyn, tid, 0, rows_left, Asrc, 1024, Bsrc, H1);
    g_issue(dyn + STG1, tid, 1, rows_left, Asrc, 1024, Bsrc, H1);

    for (int kt = 0; kt < 32; kt++) {
        if (kt < 30) CP_WAIT1(); else CP_WAIT0();
        __syncthreads();
        if (kt + 2 < 32)
            g_issue(dyn + ((kt + 2) % 3) * STG1, tid, kt + 2, rows_left, Asrc, 1024, Bsrc, H1);
        g_mma(dyn + (kt % 3) * STG1, warpM, warpN, acc);
    }

    __syncthreads();
    float (*Cs)[LDC1] = reinterpret_cast<float(*)[LDC1]>(dyn);
    #pragma unroll
    for (int m = 0; m < 2; m++)
        #pragma unroll
        for (int n = 0; n < 4; n++)
            wmma::store_matrix_sync(&Cs[warpM * 32 + m * 16][warpN * 64 + n * 16],
                                    acc[m][n], LDC1, wmma::mem_row_major);
    __syncthreads();
    #pragma unroll
    for (int q = 0; q < 32; q++) {
        int idx = q * 256 + tid;
        int r = idx >> 6, c2 = (idx & 63) * 2;
        int gi = i0 + r;
        if (gi < N_NODES) {
            float2 v;
            v.x = fmaxf(Cs[r][c2] + __ldg(&b1[n0 + c2]), 0.f);
            v.y = fmaxf(Cs[r][c2 + 1] + __ldg(&b1[n0 + c2 + 1]), 0.f);
            *reinterpret_cast<__half2*>(&g_hs[(size_t)gi * 512 + n0 + c2]) = __float22half2_rn(v);
        }
    }
}

// ================= GEMM2 (1-term): y = dinv*(h_hi @ W23_hi + demo @ Wg[256:] + c2) =================
__global__ __launch_bounds__(256) void k_gemm2(const float* __restrict__ x,
                                               const float* __restrict__ Wg) {
    extern __shared__ __align__(128) char dyn[];
    __shared__ float demoS[128][10];
    __shared__ float WgbS[10][DG];
    __shared__ float c2S[DG];

    const int i0 = blockIdx.x * 128;
    const int tid = threadIdx.x;
    const int wid = tid >> 5;
    const int warpM = wid & 3, warpN = wid >> 2;
    const int rows_left = N_NODES - i0;
    const __half* Asrc = g_hs + (size_t)i0 * 512;

    for (int idx = tid; idx < 128 * 10; idx += 256) {
        int r = idx / 10, t = idx % 10;
        int gi = i0 + r;
        demoS[r][t] = (gi < N_NODES) ? x[(size_t)gi * XDIM + SUBJ + t] : 0.f;
    }
    for (int idx = tid; idx < 10 * DG; idx += 256) {
        int t = idx >> 7, c = idx & 127;
        WgbS[t][c] = Wg[(H2 + t) * DG + c];
    }
    if (tid < DG) c2S[tid] = g_c2[tid];

    wmma::fragment<wmma::accumulator, 16, 16, 16, float> acc[2][4];
    #pragma unroll
    for (int m = 0; m < 2; m++)
        #pragma unroll
        for (int n = 0; n < 4; n++) wmma::fill_fragment(acc[m][n], 0.f);

    g_issue(dyn, tid, 0, rows_left, Asrc, 512, g_w23h, DG);
    g_issue(dyn + STG1, tid, 1, rows_left, Asrc, 512, g_w23h, DG);

    for (int kt = 0; kt < 16; kt++) {
        if (kt < 14) CP_WAIT1(); else CP_WAIT0();
        __syncthreads();
        if (kt + 2 < 16)
            g_issue(dyn + ((kt + 2) % 3) * STG1, tid, kt + 2, rows_left, Asrc, 512, g_w23h, DG);
        g_mma(dyn + (kt % 3) * STG1, warpM, warpN, acc);
    }

    __syncthreads();
    float (*Cs)[LDC1] = reinterpret_cast<float(*)[LDC1]>(dyn);
    #pragma unroll
    for (int m = 0; m < 2; m++)
        #pragma unroll
        for (int n = 0; n < 4; n++)
            wmma::store_matrix_sync(&Cs[warpM * 32 + m * 16][warpN * 64 + n * 16],
                                    acc[m][n], LDC1, wmma::mem_row_major);
    __syncthreads();
    #pragma unroll
    for (int q = 0; q < 64; q++) {
        int idx = q * 256 + tid;
        int r = idx >> 7, c = idx & 127;
        int gi = i0 + r;
        if (gi < N_NODES) {
            float v = Cs[r][c] + c2S[c];
            #pragma unroll
            for (int t = 0; t < 10; t++) v += demoS[r][t] * WgbS[t][c];
            float dinv = rsqrtf((float)g_deg[gi]);
            g_y[(size_t)gi * DG + c] = dinv * v;
        }
    }
}

// ---------------- gather + fused epilogue ----------------
__global__ __launch_bounds__(256) void k_gather(const float* __restrict__ bg,
                                                const float* __restrict__ Wo) {
    int wid = threadIdx.x >> 5, lane = threadIdx.x & 31;
    int node = blockIdx.x * 8 + wid;
    float dot = 0.f;
    if (node < N_NODES) {
        int deg = g_deg[node];
        int beg = g_off[node];
        int cnt = deg - 1;
        float4 a = *reinterpret_cast<const float4*>(&g_y[(size_t)node * DG + lane * 4]);
        #pragma unroll 4
        for (int j = 0; j < cnt; j++) {
            int s = __ldg(&g_es[beg + j]);
            float4 v = *reinterpret_cast<const float4*>(&g_y[(size_t)s * DG + lane * 4]);
            a.x += v.x; a.y += v.y; a.z += v.z; a.w += v.w;
        }
        float dinv = rsqrtf((float)deg);
        float4 bgv = *reinterpret_cast<const float4*>(&bg[lane * 4]);
        float4 wv = *reinterpret_cast<const float4*>(&Wo[lane * 4]);
        dot += fmaxf(dinv * a.x + bgv.x, 0.f) * wv.x;
        dot += fmaxf(dinv * a.y + bgv.y, 0.f) * wv.y;
        dot += fmaxf(dinv * a.z + bgv.z, 0.f) * wv.z;
        dot += fmaxf(dinv * a.w + bgv.w, 0.f) * wv.w;
    }
    #pragma unroll
    for (int o = 16; o; o >>= 1) dot += __shfl_down_sync(0xffffffffu, dot, o);
    __shared__ float part[8];
    if (lane == 0) part[wid] = dot;
    __syncthreads();
    if (threadIdx.x == 0) {
        float s = 0.f;
        #pragma unroll
        for (int w = 0; w < 8; w++) s += part[w];
        atomicAdd(&g_acc, (double)s);
    }
}

__global__ void k_fin(const float* __restrict__ bo, float* __restrict__ out) {
    out[0] = (float)(g_acc * (1.0 / (double)N_NODES) + (double)bo[0]);
}

// ---------------- launch ----------------
extern "C" void kernel_launch(void* const* d_in, const int* in_sizes, int n_in,
                              void* d_out, int out_size) {
    const float* x  = (const float*)d_in[0];
    const int*   ei = (const int*)d_in[1];
    const float* W1 = (const float*)d_in[2];
    const float* b1 = (const float*)d_in[3];
    const float* W2 = (const float*)d_in[4];
    const float* b2 = (const float*)d_in[5];
    const float* Wg = (const float*)d_in[6];
    const float* bg = (const float*)d_in[7];
    const float* Wo = (const float*)d_in[8];
    const float* bo = (const float*)d_in[9];
    float* out = (float*)d_out;

    cudaFuncSetAttribute(k_gemm1, cudaFuncAttributeMaxDynamicSharedMemorySize, DYN1);
    cudaFuncSetAttribute(k_gemm2, cudaFuncAttributeMaxDynamicSharedMemorySize, DYN1);

    k_splitx<<<2048, 256>>>(x);                                   // 1
    k_splitw<<<(1024 * 256 + 255) / 256, 256>>>(W1);              // 2
    k_init<<<(N_NODES + 255) / 256, 256>>>();                     // 3
    k_gemm1<<<G1_MBLK * 4, 256, DYN1>>>(b1);                      // 4 <- ncu capture slot
    k_deg<<<4096, 256>>>(ei);                                     // 5
    k_scan1<<<SCAN_NBLK, SCAN_CHUNK>>>();                         // 6
    k_scan2<<<1, 128>>>();                                        // 7
    k_scan3<<<SCAN_NBLK, SCAN_CHUNK>>>();                         // 8
    k_fill<<<4096, 256>>>(ei);                                    // 9
    k_pre<<<H1 + 1, 128>>>(W2, Wg, b2);                           // 10
    k_gemm2<<<(N_NODES + 127) / 128, 256, DYN1>>>(x, Wg);         // 11
    k_gather<<<(N_NODES + 7) / 8, 256>>>(bg, Wo);                 // 12
    k_fin<<<1, 1>>>(bo, out);                                     // 13
}

// round 13
// speedup vs baseline: 1.6485x; 1.1338x over previous
#include <cuda_runtime.h>
#include <cuda_fp16.h>
#include <mma.h>
#include <cstdint>

using namespace nvcuda;

#define N_NODES 100000
#define N_EDGESC 1600000
#define XDIM 1010
#define SUBJ 1000
#define H1 512
#define H2 256
#define DG 128

// ---------------- static device scratch ----------------
__device__ __half g_xs[(size_t)N_NODES * 1024];   // x hi (K padded to 1024)
__device__ __half g_w1h[1024 * H1];               // W1 hi
__device__ __half g_hs[(size_t)N_NODES * 512];    // h hi only
__device__ __half g_w23h[H1 * DG];                // folded W2@Wg hi only
__device__ float  g_c2[DG];
__device__ __half g_y2[(size_t)N_NODES * DG];     // y in fp16
__device__ int    g_deg[N_NODES];
__device__ int    g_off[N_NODES];
__device__ int    g_cur[N_NODES];
__device__ int    g_es[N_EDGESC];
__device__ int    g_bsum[128];
__device__ double g_acc;

// ---------------- helpers ----------------
__device__ __forceinline__ uint32_t smem_u32(const void* p) {
    uint32_t a;
    asm("{ .reg .u64 t; cvta.to.shared.u64 t, %1; cvt.u32.u64 %0, t; }" : "=r"(a) : "l"(p));
    return a;
}
#define CP_A16(dst, src, n) \
    asm volatile("cp.async.cg.shared.global [%0], [%1], 16, %2;" :: "r"(dst), "l"(src), "r"(n))
#define CP_COMMIT() asm volatile("cp.async.commit_group;" ::: "memory")
#define CP_WAIT0()  asm volatile("cp.async.wait_group 0;" ::: "memory")
#define CP_WAIT1()  asm volatile("cp.async.wait_group 1;" ::: "memory")

// ---------------- x -> fp16 hi ----------------
__global__ void k_splitx(const float* __restrict__ x) {
    for (long long id = (long long)blockIdx.x * blockDim.x + threadIdx.x;
         id < (long long)N_NODES * 512; id += (long long)gridDim.x * blockDim.x) {
        int row = (int)(id >> 9);
        int col = (int)(id & 511) * 2;
        float2 v = make_float2(0.f, 0.f);
        if (col < SUBJ) v = *reinterpret_cast<const float2*>(&x[(size_t)row * XDIM + col]);
        *reinterpret_cast<__half2*>(&g_xs[(size_t)row * 1024 + col]) = __float22half2_rn(v);
    }
}

// ---------------- W1 -> fp16 hi ----------------
__global__ void k_splitw(const float* __restrict__ W1) {
    int id = blockIdx.x * blockDim.x + threadIdx.x;
    if (id >= 1024 * 256) return;
    int row = id >> 8;
    int col = (id & 255) * 2;
    float2 v = make_float2(0.f, 0.f);
    if (row < SUBJ) v = *reinterpret_cast<const float2*>(&W1[(size_t)row * H1 + col]);
    *reinterpret_cast<__half2*>(&g_w1h[row * H1 + col]) = __float22half2_rn(v);
}

// ---------------- init ----------------
__global__ void k_init() {
    int i = blockIdx.x * blockDim.x + threadIdx.x;
    if (i < N_NODES) g_deg[i] = 1;
    if (i == 0) g_acc = 0.0;
}

// ---------------- weight fold (fp16 hi) ----------------
__global__ void k_pre(const float* __restrict__ W2, const float* __restrict__ Wg,
                      const float* __restrict__ b2) {
    int k = blockIdx.x;
    int j = threadIdx.x;
    if (k < H1) {
        __shared__ float row[H2];
        for (int m = j; m < H2; m += 128) row[m] = W2[k * H2 + m];
        __syncthreads();
        float acc = 0.f;
        #pragma unroll 4
        for (int m = 0; m < H2; m++) acc += row[m] * Wg[m * DG + j];
        g_w23h[k * DG + j] = __float2half_rn(acc);
    } else {
        float acc = 0.f;
        for (int m = 0; m < H2; m++) acc += b2[m] * Wg[m * DG + j];
        g_c2[j] = acc;
    }
}

// ---------------- degree count ----------------
__global__ void k_deg(const int* __restrict__ ei) {
    for (int e = blockIdx.x * blockDim.x + threadIdx.x; e < N_EDGESC;
         e += gridDim.x * blockDim.x) {
        int dst = ei[N_EDGESC + e];
        dst = min(max(dst, 0), N_NODES - 1);
        atomicAdd(&g_deg[dst], 1);
    }
}

// ---------------- multi-block scan ----------------
#define SCAN_CHUNK 1024
#define SCAN_NBLK ((N_NODES + SCAN_CHUNK - 1) / SCAN_CHUNK)  // 98

__global__ void k_scan1() {
    __shared__ int wsum[32];
    int i = blockIdx.x * SCAN_CHUNK + threadIdx.x;
    int v = (i < N_NODES) ? (g_deg[i] - 1) : 0;
    #pragma unroll
    for (int o = 16; o; o >>= 1) v += __shfl_down_sync(0xffffffffu, v, o);
    int lane = threadIdx.x & 31, wid = threadIdx.x >> 5;
    if (lane == 0) wsum[wid] = v;
    __syncthreads();
    if (wid == 0) {
        int t = wsum[lane];
        #pragma unroll
        for (int o = 16; o; o >>= 1) t += __shfl_down_sync(0xffffffffu, t, o);
        if (lane == 0) g_bsum[blockIdx.x] = t;
    }
}

__global__ void k_scan2() {
    __shared__ int wtot[4];
    int tid = threadIdx.x, lane = tid & 31, wid = tid >> 5;
    int v = (tid < SCAN_NBLK) ? g_bsum[tid] : 0;
    int s = v;
    #pragma unroll
    for (int o = 1; o < 32; o <<= 1) {
        int t = __shfl_up_sync(0xffffffffu, s, o);
        if (lane >= o) s += t;
    }
    if (lane == 31) wtot[wid] = s;
    __syncthreads();
    int base = 0;
    for (int w = 0; w < wid; w++) base += wtot[w];
    if (tid < SCAN_NBLK) g_bsum[tid] = base + s - v;
}

__global__ void k_scan3() {
    __shared__ int wpre[32];
    int tid = threadIdx.x, lane = tid & 31, wid = tid >> 5;
    int i = blockIdx.x * SCAN_CHUNK + tid;
    int v = (i < N_NODES) ? (g_deg[i] - 1) : 0;
    int s = v;
    #pragma unroll
    for (int o = 1; o < 32; o <<= 1) {
        int t = __shfl_up_sync(0xffffffffu, s, o);
        if (lane >= o) s += t;
    }
    if (lane == 31) wpre[wid] = s;
    __syncthreads();
    if (wid == 0) {
        int t = wpre[lane];
        #pragma unroll
        for (int o = 1; o < 32; o <<= 1) {
            int u = __shfl_up_sync(0xffffffffu, t, o);
            if (lane >= o) t += u;
        }
        wpre[lane] = t;
    }
    __syncthreads();
    int excl = s - v + (wid > 0 ? wpre[wid - 1] : 0) + g_bsum[blockIdx.x];
    if (i < N_NODES) { g_off[i] = excl; g_cur[i] = excl; }
}

// ---------------- CSR fill ----------------
__global__ void k_fill(const int* __restrict__ ei) {
    for (int e = blockIdx.x * blockDim.x + threadIdx.x; e < N_EDGESC;
         e += gridDim.x * blockDim.x) {
        int src = ei[e];
        int dst = ei[N_EDGESC + e];
        src = min(max(src, 0), N_NODES - 1);
        dst = min(max(dst, 0), N_NODES - 1);
        int pos = atomicAdd(&g_cur[dst], 1);
        g_es[pos] = src;
    }
}

// ================= GEMM1: BM=128 BN=128 BK=64, 3-stage, 1-term fp16 =================
// N-fastest 1D grid (A rows DRAM once, L2 3x).
// stage: AH[128x72] 18432 | BH[64x136] 17408 => 35840; x3 = 107520 (2 CTAs/SM).
#define LDA1 72
#define LDB1 136
#define LDC1 136
#define S1_OFF_BH 18432
#define STG1 35840
#define DYN1 107520              // 3*STG1; epilogue 69632 < this
#define G1_MBLK ((N_NODES + 127) / 128)   // 782

__device__ __forceinline__ void g1_issue(char* st, int tid, int kt, int rows_left,
                                         const __half* Asrc, const __half* Bsrc) {
    const int k0 = kt * 64;
    const uint32_t ah = smem_u32(st);
    const uint32_t bh = ah + S1_OFF_BH;
    // A: 128 rows x 8 chunks of 16B
    #pragma unroll
    for (int p = 0; p < 4; p++) {
        int idx = tid + p * 256;
        int row = idx >> 3;
        int ch = idx & 7;
        int n = (row < rows_left) ? 16 : 0;
        const __half* s = Asrc + (size_t)row * 1024 + k0 + ch * 8;
        CP_A16(ah + row * (LDA1 * 2) + ch * 16, s, n);
    }
    // B: 64 rows x 16 chunks of 16B
    #pragma unroll
    for (int p = 0; p < 4; p++) {
        int idx = tid + p * 256;
        int row = idx >> 4;
        int ch = idx & 15;
        const __half* sh = Bsrc + (size_t)(k0 + row) * H1 + ch * 8;
        CP_A16(bh + row * (LDB1 * 2) + ch * 16, sh, 16);
    }
    CP_COMMIT();
}

__global__ __launch_bounds__(256) void k_gemm1(const float* __restrict__ b1) {
    extern __shared__ __align__(128) char dyn[];
    const int bx = blockIdx.x;
    const int i0 = (bx >> 2) * 128;
    const int n0 = (bx & 3) * 128;
    const int tid = threadIdx.x;
    const int wid = tid >> 5;
    const int warpM = wid & 3, warpN = wid >> 2;   // 4x2 warps, warp tile 32x64
    const int rows_left = N_NODES - i0;
    const __half* Asrc = g_xs + (size_t)i0 * 1024;
    const __half* Bsrc = g_w1h + n0;

    wmma::fragment<wmma::accumulator, 16, 16, 16, float> acc[2][4];
    #pragma unroll
    for (int m = 0; m < 2; m++)
        #pragma unroll
        for (int n = 0; n < 4; n++) wmma::fill_fragment(acc[m][n], 0.f);

    g1_issue(dyn, tid, 0, rows_left, Asrc, Bsrc);
    g1_issue(dyn + STG1, tid, 1, rows_left, Asrc, Bsrc);

    for (int kt = 0; kt < 16; kt++) {
        if (kt < 14) CP_WAIT1(); else CP_WAIT0();
        __syncthreads();
        if (kt + 2 < 16) g1_issue(dyn + ((kt + 2) % 3) * STG1, tid, kt + 2, rows_left, Asrc, Bsrc);
        char* st = dyn + (kt % 3) * STG1;
        __half (*Ah)[LDA1] = reinterpret_cast<__half(*)[LDA1]>(st);
        __half (*Bh)[LDB1] = reinterpret_cast<__half(*)[LDB1]>(st + S1_OFF_BH);
        #pragma unroll
        for (int kk = 0; kk < 64; kk += 16) {
            wmma::fragment<wmma::matrix_a, 16, 16, 16, __half, wmma::row_major> afH[2];
            #pragma unroll
            for (int m = 0; m < 2; m++)
                wmma::load_matrix_sync(afH[m], &Ah[warpM * 32 + m * 16][kk], LDA1);
            #pragma unroll
            for (int n = 0; n < 4; n++) {
                wmma::fragment<wmma::matrix_b, 16, 16, 16, __half, wmma::row_major> bfH;
                wmma::load_matrix_sync(bfH, &Bh[kk][warpN * 64 + n * 16], LDB1);
                #pragma unroll
                for (int m = 0; m < 2; m++)
                    wmma::mma_sync(acc[m][n], afH[m], bfH, acc[m][n]);
            }
        }
    }

    __syncthreads();
    float (*Cs)[LDC1] = reinterpret_cast<float(*)[LDC1]>(dyn);
    #pragma unroll
    for (int m = 0; m < 2; m++)
        #pragma unroll
        for (int n = 0; n < 4; n++)
            wmma::store_matrix_sync(&Cs[warpM * 32 + m * 16][warpN * 64 + n * 16],
                                    acc[m][n], LDC1, wmma::mem_row_major);
    __syncthreads();
    #pragma unroll
    for (int q = 0; q < 32; q++) {
        int idx = q * 256 + tid;
        int r = idx >> 6, c2 = (idx & 63) * 2;
        int gi = i0 + r;
        if (gi < N_NODES) {
            float2 v;
            v.x = fmaxf(Cs[r][c2] + __ldg(&b1[n0 + c2]), 0.f);
            v.y = fmaxf(Cs[r][c2 + 1] + __ldg(&b1[n0 + c2 + 1]), 0.f);
            *reinterpret_cast<__half2*>(&g_hs[(size_t)gi * 512 + n0 + c2]) = __float22half2_rn(v);
        }
    }
}

// ================= GEMM2 (1-term, BK=32, 3-stage): y2 = fp16(dinv*(h_hi @ W23_hi + demo @ Wg[256:] + c2)) =================
#define LDA2 40
#define LDB2 136
#define S2_OFF_BH 10240
#define STG2 18944
#define DYN2 69632               // max(3*STG2=56832, epilogue 69632)

__device__ __forceinline__ void g2_issue(char* st, int tid, int kt, int rows_left,
                                         const __half* Asrc) {
    const int k0 = kt * 32;
    const uint32_t ah = smem_u32(st);
    const uint32_t bh = ah + S2_OFF_BH;
    #pragma unroll
    for (int p = 0; p < 2; p++) {
        int idx = tid + p * 256;
        int row = idx >> 2;
        int ch = idx & 3;
        int n = (row < rows_left) ? 16 : 0;
        const __half* s = Asrc + (size_t)row * 512 + k0 + ch * 8;
        CP_A16(ah + row * (LDA2 * 2) + ch * 16, s, n);
    }
    #pragma unroll
    for (int p = 0; p < 2; p++) {
        int idx = tid + p * 256;
        int row = idx >> 4;
        int ch = idx & 15;
        const __half* sh = g_w23h + (size_t)(k0 + row) * DG + ch * 8;
        CP_A16(bh + row * (LDB2 * 2) + ch * 16, sh, 16);
    }
    CP_COMMIT();
}

__global__ __launch_bounds__(256) void k_gemm2(const float* __restrict__ x,
                                               const float* __restrict__ Wg) {
    extern __shared__ __align__(128) char dyn[];
    __shared__ float demoS[128][10];
    __shared__ float WgbS[10][DG];
    __shared__ float c2S[DG];

    const int i0 = blockIdx.x * 128;
    const int tid = threadIdx.x;
    const int wid = tid >> 5;
    const int warpM = wid & 3, warpN = wid >> 2;
    const int rows_left = N_NODES - i0;
    const __half* Asrc = g_hs + (size_t)i0 * 512;

    for (int idx = tid; idx < 128 * 10; idx += 256) {
        int r = idx / 10, t = idx % 10;
        int gi = i0 + r;
        demoS[r][t] = (gi < N_NODES) ? x[(size_t)gi * XDIM + SUBJ + t] : 0.f;
    }
    for (int idx = tid; idx < 10 * DG; idx += 256) {
        int t = idx >> 7, c = idx & 127;
        WgbS[t][c] = Wg[(H2 + t) * DG + c];
    }
    if (tid < DG) c2S[tid] = g_c2[tid];

    wmma::fragment<wmma::accumulator, 16, 16, 16, float> acc[2][4];
    #pragma unroll
    for (int m = 0; m < 2; m++)
        #pragma unroll
        for (int n = 0; n < 4; n++) wmma::fill_fragment(acc[m][n], 0.f);

    g2_issue(dyn, tid, 0, rows_left, Asrc);
    g2_issue(dyn + STG2, tid, 1, rows_left, Asrc);

    for (int kt = 0; kt < 16; kt++) {
        if (kt < 14) CP_WAIT1(); else CP_WAIT0();
        __syncthreads();
        if (kt + 2 < 16) g2_issue(dyn + ((kt + 2) % 3) * STG2, tid, kt + 2, rows_left, Asrc);
        char* st = dyn + (kt % 3) * STG2;
        __half (*Ah)[LDA2] = reinterpret_cast<__half(*)[LDA2]>(st);
        __half (*Bh)[LDB2] = reinterpret_cast<__half(*)[LDB2]>(st + S2_OFF_BH);
        #pragma unroll
        for (int kk = 0; kk < 32; kk += 16) {
            wmma::fragment<wmma::matrix_a, 16, 16, 16, __half, wmma::row_major> afH[2];
            #pragma unroll
            for (int m = 0; m < 2; m++)
                wmma::load_matrix_sync(afH[m], &Ah[warpM * 32 + m * 16][kk], LDA2);
            #pragma unroll
            for (int n = 0; n < 4; n++) {
                wmma::fragment<wmma::matrix_b, 16, 16, 16, __half, wmma::row_major> bfH;
                wmma::load_matrix_sync(bfH, &Bh[kk][warpN * 64 + n * 16], LDB2);
                #pragma unroll
                for (int m = 0; m < 2; m++)
                    wmma::mma_sync(acc[m][n], afH[m], bfH, acc[m][n]);
            }
        }
    }

    __syncthreads();
    float (*Cs)[LDC1] = reinterpret_cast<float(*)[LDC1]>(dyn);
    #pragma unroll
    for (int m = 0; m < 2; m++)
        #pragma unroll
        for (int n = 0; n < 4; n++)
            wmma::store_matrix_sync(&Cs[warpM * 32 + m * 16][warpN * 64 + n * 16],
                                    acc[m][n], LDC1, wmma::mem_row_major);
    __syncthreads();
    #pragma unroll
    for (int q = 0; q < 32; q++) {
        int idx = q * 256 + tid;
        int r = idx >> 6, c2 = (idx & 63) * 2;
        int gi = i0 + r;
        if (gi < N_NODES) {
            float v0 = Cs[r][c2] + c2S[c2];
            float v1 = Cs[r][c2 + 1] + c2S[c2 + 1];
            #pragma unroll
            for (int t = 0; t < 10; t++) {
                float d = demoS[r][t];
                v0 += d * WgbS[t][c2];
                v1 += d * WgbS[t][c2 + 1];
            }
            float dinv = rsqrtf((float)g_deg[gi]);
            *reinterpret_cast<__half2*>(&g_y2[(size_t)gi * DG + c2]) =
                __floats2half2_rn(dinv * v0, dinv * v1);
        }
    }
}

// ---------------- gather (fp16 y) + fused epilogue ----------------
__global__ __launch_bounds__(256) void k_gather(const float* __restrict__ bg,
                                                const float* __restrict__ Wo) {
    int wid = threadIdx.x >> 5, lane = threadIdx.x & 31;
    int node = blockIdx.x * 8 + wid;
    float dot = 0.f;
    if (node < N_NODES) {
        int deg = g_deg[node];
        int beg = g_off[node];
        int cnt = deg - 1;
        float2 raw = *reinterpret_cast<const float2*>(&g_y2[(size_t)node * DG + lane * 4]);
        __half2 h0 = *reinterpret_cast<__half2*>(&raw.x);
        __half2 h1 = *reinterpret_cast<__half2*>(&raw.y);
        float2 f0 = __half22float2(h0), f1 = __half22float2(h1);
        float4 a = make_float4(f0.x, f0.y, f1.x, f1.y);
        #pragma unroll 4
        for (int j = 0; j < cnt; j++) {
            int s = __ldg(&g_es[beg + j]);
            float2 rw = *reinterpret_cast<const float2*>(&g_y2[(size_t)s * DG + lane * 4]);
            __half2 g0 = *reinterpret_cast<__half2*>(&rw.x);
            __half2 g1 = *reinterpret_cast<__half2*>(&rw.y);
            float2 e0 = __half22float2(g0), e1 = __half22float2(g1);
            a.x += e0.x; a.y += e0.y; a.z += e1.x; a.w += e1.y;
        }
        float dinv = rsqrtf((float)deg);
        float4 bgv = *reinterpret_cast<const float4*>(&bg[lane * 4]);
        float4 wv = *reinterpret_cast<const float4*>(&Wo[lane * 4]);
        dot += fmaxf(dinv * a.x + bgv.x, 0.f) * wv.x;
        dot += fmaxf(dinv * a.y + bgv.y, 0.f) * wv.y;
        dot += fmaxf(dinv * a.z + bgv.z, 0.f) * wv.z;
        dot += fmaxf(dinv * a.w + bgv.w, 0.f) * wv.w;
    }
    #pragma unroll
    for (int o = 16; o; o >>= 1) dot += __shfl_down_sync(0xffffffffu, dot, o);
    __shared__ float part[8];
    if (lane == 0) part[wid] = dot;
    __syncthreads();
    if (threadIdx.x == 0) {
        float s = 0.f;
        #pragma unroll
        for (int w = 0; w < 8; w++) s += part[w];
        atomicAdd(&g_acc, (double)s);
    }
}

__global__ void k_fin(const float* __restrict__ bo, float* __restrict__ out) {
    out[0] = (float)(g_acc * (1.0 / (double)N_NODES) + (double)bo[0]);
}

// ---------------- launch ----------------
extern "C" void kernel_launch(void* const* d_in, const int* in_sizes, int n_in,
                              void* d_out, int out_size) {
    const float* x  = (const float*)d_in[0];
    const int*   ei = (const int*)d_in[1];
    const float* W1 = (const float*)d_in[2];
    const float* b1 = (const float*)d_in[3];
    const float* W2 = (const float*)d_in[4];
    const float* b2 = (const float*)d_in[5];
    const float* Wg = (const float*)d_in[6];
    const float* bg = (const float*)d_in[7];
    const float* Wo = (const float*)d_in[8];
    const float* bo = (const float*)d_in[9];
    float* out = (float*)d_out;

    cudaFuncSetAttribute(k_gemm1, cudaFuncAttributeMaxDynamicSharedMemorySize, DYN1);
    cudaFuncSetAttribute(k_gemm2, cudaFuncAttributeMaxDynamicSharedMemorySize, DYN2);

    k_splitx<<<2048, 256>>>(x);                                   // 1
    k_splitw<<<(1024 * 256 + 255) / 256, 256>>>(W1);              // 2
    k_init<<<(N_NODES + 255) / 256, 256>>>();                     // 3
    k_gemm1<<<G1_MBLK * 4, 256, DYN1>>>(b1);                      // 4 <- ncu capture slot
    k_deg<<<4096, 256>>>(ei);                                     // 5
    k_scan1<<<SCAN_NBLK, SCAN_CHUNK>>>();                         // 6
    k_scan2<<<1, 128>>>();                                        // 7
    k_scan3<<<SCAN_NBLK, SCAN_CHUNK>>>();                         // 8
    k_fill<<<4096, 256>>>(ei);                                    // 9
    k_pre<<<H1 + 1, 128>>>(W2, Wg, b2);                           // 10
    k_gemm2<<<(N_NODES + 127) / 128, 256, DYN2>>>(x, Wg);         // 11
    k_gather<<<(N_NODES + 7) / 8, 256>>>(bg, Wo);                 // 12
    k_fin<<<1, 1>>>(bo, out);                                     // 13
}

// round 14
// speedup vs baseline: 1.7408x; 1.0559x over previous
#include <cuda_runtime.h>
#include <cuda_fp16.h>
#include <mma.h>
#include <cstdint>

using namespace nvcuda;

#define N_NODES 100000
#define N_EDGESC 1600000
#define XDIM 1010
#define SUBJ 1000
#define H1 512
#define H2 256
#define DG 128

// ---------------- static device scratch ----------------
__device__ __half g_xs[(size_t)N_NODES * 1024];   // x hi (K padded to 1024)
__device__ __half g_w1h[1024 * H1];               // W1 hi
__device__ __half g_hs[(size_t)N_NODES * 512];    // h hi only
__device__ __half g_w23h[H1 * DG];                // folded W2@Wg hi only
__device__ float  g_c2[DG];
__device__ __half g_y2[(size_t)N_NODES * DG];     // y in fp16
__device__ int    g_deg[N_NODES];
__device__ int    g_off[N_NODES];
__device__ int    g_cur[N_NODES];
__device__ int    g_es[N_EDGESC];
__device__ int    g_bsum[128];
__device__ double g_acc;

// ---------------- helpers ----------------
__device__ __forceinline__ uint32_t smem_u32(const void* p) {
    uint32_t a;
    asm("{ .reg .u64 t; cvta.to.shared.u64 t, %1; cvt.u32.u64 %0, t; }" : "=r"(a) : "l"(p));
    return a;
}
#define CP_A16(dst, src, n) \
    asm volatile("cp.async.cg.shared.global [%0], [%1], 16, %2;" :: "r"(dst), "l"(src), "r"(n))
#define CP_COMMIT() asm volatile("cp.async.commit_group;" ::: "memory")
#define CP_WAIT0()  asm volatile("cp.async.wait_group 0;" ::: "memory")
#define CP_WAIT1()  asm volatile("cp.async.wait_group 1;" ::: "memory")

// ---------------- x -> fp16 hi ----------------
__global__ void k_splitx(const float* __restrict__ x) {
    for (long long id = (long long)blockIdx.x * blockDim.x + threadIdx.x;
         id < (long long)N_NODES * 512; id += (long long)gridDim.x * blockDim.x) {
        int row = (int)(id >> 9);
        int col = (int)(id & 511) * 2;
        float2 v = make_float2(0.f, 0.f);
        if (col < SUBJ) v = *reinterpret_cast<const float2*>(&x[(size_t)row * XDIM + col]);
        *reinterpret_cast<__half2*>(&g_xs[(size_t)row * 1024 + col]) = __float22half2_rn(v);
    }
}

// ---------------- W1 -> fp16 hi ----------------
__global__ void k_splitw(const float* __restrict__ W1) {
    int id = blockIdx.x * blockDim.x + threadIdx.x;
    if (id >= 1024 * 256) return;
    int row = id >> 8;
    int col = (id & 255) * 2;
    float2 v = make_float2(0.f, 0.f);
    if (row < SUBJ) v = *reinterpret_cast<const float2*>(&W1[(size_t)row * H1 + col]);
    *reinterpret_cast<__half2*>(&g_w1h[row * H1 + col]) = __float22half2_rn(v);
}

// ---------------- init ----------------
__global__ void k_init() {
    int i = blockIdx.x * blockDim.x + threadIdx.x;
    if (i < N_NODES) g_deg[i] = 1;
    if (i == 0) g_acc = 0.0;
}

// ---------------- weight fold (fp16 hi) ----------------
__global__ void k_pre(const float* __restrict__ W2, const float* __restrict__ Wg,
                      const float* __restrict__ b2) {
    int k = blockIdx.x;
    int j = threadIdx.x;
    if (k < H1) {
        __shared__ float row[H2];
        for (int m = j; m < H2; m += 128) row[m] = W2[k * H2 + m];
        __syncthreads();
        float acc = 0.f;
        #pragma unroll 4
        for (int m = 0; m < H2; m++) acc += row[m] * Wg[m * DG + j];
        g_w23h[k * DG + j] = __float2half_rn(acc);
    } else {
        float acc = 0.f;
        for (int m = 0; m < H2; m++) acc += b2[m] * Wg[m * DG + j];
        g_c2[j] = acc;
    }
}

// ---------------- degree count ----------------
__global__ void k_deg(const int* __restrict__ ei) {
    for (int e = blockIdx.x * blockDim.x + threadIdx.x; e < N_EDGESC;
         e += gridDim.x * blockDim.x) {
        int dst = ei[N_EDGESC + e];
        dst = min(max(dst, 0), N_NODES - 1);
        atomicAdd(&g_deg[dst], 1);
    }
}

// ---------------- multi-block scan ----------------
#define SCAN_CHUNK 1024
#define SCAN_NBLK ((N_NODES + SCAN_CHUNK - 1) / SCAN_CHUNK)  // 98

__global__ void k_scan1() {
    __shared__ int wsum[32];
    int i = blockIdx.x * SCAN_CHUNK + threadIdx.x;
    int v = (i < N_NODES) ? (g_deg[i] - 1) : 0;
    #pragma unroll
    for (int o = 16; o; o >>= 1) v += __shfl_down_sync(0xffffffffu, v, o);
    int lane = threadIdx.x & 31, wid = threadIdx.x >> 5;
    if (lane == 0) wsum[wid] = v;
    __syncthreads();
    if (wid == 0) {
        int t = wsum[lane];
        #pragma unroll
        for (int o = 16; o; o >>= 1) t += __shfl_down_sync(0xffffffffu, t, o);
        if (lane == 0) g_bsum[blockIdx.x] = t;
    }
}

__global__ void k_scan2() {
    __shared__ int wtot[4];
    int tid = threadIdx.x, lane = tid & 31, wid = tid >> 5;
    int v = (tid < SCAN_NBLK) ? g_bsum[tid] : 0;
    int s = v;
    #pragma unroll
    for (int o = 1; o < 32; o <<= 1) {
        int t = __shfl_up_sync(0xffffffffu, s, o);
        if (lane >= o) s += t;
    }
    if (lane == 31) wtot[wid] = s;
    __syncthreads();
    int base = 0;
    for (int w = 0; w < wid; w++) base += wtot[w];
    if (tid < SCAN_NBLK) g_bsum[tid] = base + s - v;
}

__global__ void k_scan3() {
    __shared__ int wpre[32];
    int tid = threadIdx.x, lane = tid & 31, wid = tid >> 5;
    int i = blockIdx.x * SCAN_CHUNK + tid;
    int v = (i < N_NODES) ? (g_deg[i] - 1) : 0;
    int s = v;
    #pragma unroll
    for (int o = 1; o < 32; o <<= 1) {
        int t = __shfl_up_sync(0xffffffffu, s, o);
        if (lane >= o) s += t;
    }
    if (lane == 31) wpre[wid] = s;
    __syncthreads();
    if (wid == 0) {
        int t = wpre[lane];
        #pragma unroll
        for (int o = 1; o < 32; o <<= 1) {
            int u = __shfl_up_sync(0xffffffffu, t, o);
            if (lane >= o) t += u;
        }
        wpre[lane] = t;
    }
    __syncthreads();
    int excl = s - v + (wid > 0 ? wpre[wid - 1] : 0) + g_bsum[blockIdx.x];
    if (i < N_NODES) { g_off[i] = excl; g_cur[i] = excl; }
}

// ---------------- CSR fill ----------------
__global__ void k_fill(const int* __restrict__ ei) {
    for (int e = blockIdx.x * blockDim.x + threadIdx.x; e < N_EDGESC;
         e += gridDim.x * blockDim.x) {
        int src = ei[e];
        int dst = ei[N_EDGESC + e];
        src = min(max(src, 0), N_NODES - 1);
        dst = min(max(dst, 0), N_NODES - 1);
        int pos = atomicAdd(&g_cur[dst], 1);
        g_es[pos] = src;
    }
}

// ================= GEMM1: BM=128 BN=128 BK=64, 3-stage, 1-term fp16 =================
#define LDA1 72
#define LDB1 136
#define LDC1 136
#define S1_OFF_BH 18432
#define STG1 35840
#define DYN1 107520
#define G1_MBLK ((N_NODES + 127) / 128)   // 782

__device__ __forceinline__ void g1_issue(char* st, int tid, int kt, int rows_left,
                                         const __half* Asrc, const __half* Bsrc) {
    const int k0 = kt * 64;
    const uint32_t ah = smem_u32(st);
    const uint32_t bh = ah + S1_OFF_BH;
    #pragma unroll
    for (int p = 0; p < 4; p++) {
        int idx = tid + p * 256;
        int row = idx >> 3;
        int ch = idx & 7;
        int n = (row < rows_left) ? 16 : 0;
        const __half* s = Asrc + (size_t)row * 1024 + k0 + ch * 8;
        CP_A16(ah + row * (LDA1 * 2) + ch * 16, s, n);
    }
    #pragma unroll
    for (int p = 0; p < 4; p++) {
        int idx = tid + p * 256;
        int row = idx >> 4;
        int ch = idx & 15;
        const __half* sh = Bsrc + (size_t)(k0 + row) * H1 + ch * 8;
        CP_A16(bh + row * (LDB1 * 2) + ch * 16, sh, 16);
    }
    CP_COMMIT();
}

__global__ __launch_bounds__(256) void k_gemm1(const float* __restrict__ b1) {
    extern __shared__ __align__(128) char dyn[];
    const int bx = blockIdx.x;
    const int i0 = (bx >> 2) * 128;
    const int n0 = (bx & 3) * 128;
    const int tid = threadIdx.x;
    const int wid = tid >> 5;
    const int warpM = wid & 3, warpN = wid >> 2;
    const int rows_left = N_NODES - i0;
    const __half* Asrc = g_xs + (size_t)i0 * 1024;
    const __half* Bsrc = g_w1h + n0;

    wmma::fragment<wmma::accumulator, 16, 16, 16, float> acc[2][4];
    #pragma unroll
    for (int m = 0; m < 2; m++)
        #pragma unroll
        for (int n = 0; n < 4; n++) wmma::fill_fragment(acc[m][n], 0.f);

    g1_issue(dyn, tid, 0, rows_left, Asrc, Bsrc);
    g1_issue(dyn + STG1, tid, 1, rows_left, Asrc, Bsrc);

    for (int kt = 0; kt < 16; kt++) {
        if (kt < 14) CP_WAIT1(); else CP_WAIT0();
        __syncthreads();
        if (kt + 2 < 16) g1_issue(dyn + ((kt + 2) % 3) * STG1, tid, kt + 2, rows_left, Asrc, Bsrc);
        char* st = dyn + (kt % 3) * STG1;
        __half (*Ah)[LDA1] = reinterpret_cast<__half(*)[LDA1]>(st);
        __half (*Bh)[LDB1] = reinterpret_cast<__half(*)[LDB1]>(st + S1_OFF_BH);
        #pragma unroll
        for (int kk = 0; kk < 64; kk += 16) {
            wmma::fragment<wmma::matrix_a, 16, 16, 16, __half, wmma::row_major> afH[2];
            #pragma unroll
            for (int m = 0; m < 2; m++)
                wmma::load_matrix_sync(afH[m], &Ah[warpM * 32 + m * 16][kk], LDA1);
            #pragma unroll
            for (int n = 0; n < 4; n++) {
                wmma::fragment<wmma::matrix_b, 16, 16, 16, __half, wmma::row_major> bfH;
                wmma::load_matrix_sync(bfH, &Bh[kk][warpN * 64 + n * 16], LDB1);
                #pragma unroll
                for (int m = 0; m < 2; m++)
                    wmma::mma_sync(acc[m][n], afH[m], bfH, acc[m][n]);
            }
        }
    }

    __syncthreads();
    float (*Cs)[LDC1] = reinterpret_cast<float(*)[LDC1]>(dyn);
    #pragma unroll
    for (int m = 0; m < 2; m++)
        #pragma unroll
        for (int n = 0; n < 4; n++)
            wmma::store_matrix_sync(&Cs[warpM * 32 + m * 16][warpN * 64 + n * 16],
                                    acc[m][n], LDC1, wmma::mem_row_major);
    __syncthreads();
    #pragma unroll
    for (int q = 0; q < 32; q++) {
        int idx = q * 256 + tid;
        int r = idx >> 6, c2 = (idx & 63) * 2;
        int gi = i0 + r;
        if (gi < N_NODES) {
            float2 v;
            v.x = fmaxf(Cs[r][c2] + __ldg(&b1[n0 + c2]), 0.f);
            v.y = fmaxf(Cs[r][c2 + 1] + __ldg(&b1[n0 + c2 + 1]), 0.f);
            *reinterpret_cast<__half2*>(&g_hs[(size_t)gi * 512 + n0 + c2]) = __float22half2_rn(v);
        }
    }
}

// ================= GEMM2 (1-term, BK=32, 3-stage) =================
#define LDA2 40
#define LDB2 136
#define S2_OFF_BH 10240
#define STG2 18944
#define DYN2 69632

__device__ __forceinline__ void g2_issue(char* st, int tid, int kt, int rows_left,
                                         const __half* Asrc) {
    const int k0 = kt * 32;
    const uint32_t ah = smem_u32(st);
    const uint32_t bh = ah + S2_OFF_BH;
    #pragma unroll
    for (int p = 0; p < 2; p++) {
        int idx = tid + p * 256;
        int row = idx >> 2;
        int ch = idx & 3;
        int n = (row < rows_left) ? 16 : 0;
        const __half* s = Asrc + (size_t)row * 512 + k0 + ch * 8;
        CP_A16(ah + row * (LDA2 * 2) + ch * 16, s, n);
    }
    #pragma unroll
    for (int p = 0; p < 2; p++) {
        int idx = tid + p * 256;
        int row = idx >> 4;
        int ch = idx & 15;
        const __half* sh = g_w23h + (size_t)(k0 + row) * DG + ch * 8;
        CP_A16(bh + row * (LDB2 * 2) + ch * 16, sh, 16);
    }
    CP_COMMIT();
}

__global__ __launch_bounds__(256) void k_gemm2(const float* __restrict__ x,
                                               const float* __restrict__ Wg) {
    extern __shared__ __align__(128) char dyn[];
    __shared__ float demoS[128][10];
    __shared__ float WgbS[10][DG];
    __shared__ float c2S[DG];

    const int i0 = blockIdx.x * 128;
    const int tid = threadIdx.x;
    const int wid = tid >> 5;
    const int warpM = wid & 3, warpN = wid >> 2;
    const int rows_left = N_NODES - i0;
    const __half* Asrc = g_hs + (size_t)i0 * 512;

    for (int idx = tid; idx < 128 * 10; idx += 256) {
        int r = idx / 10, t = idx % 10;
        int gi = i0 + r;
        demoS[r][t] = (gi < N_NODES) ? x[(size_t)gi * XDIM + SUBJ + t] : 0.f;
    }
    for (int idx = tid; idx < 10 * DG; idx += 256) {
        int t = idx >> 7, c = idx & 127;
        WgbS[t][c] = Wg[(H2 + t) * DG + c];
    }
    if (tid < DG) c2S[tid] = g_c2[tid];

    wmma::fragment<wmma::accumulator, 16, 16, 16, float> acc[2][4];
    #pragma unroll
    for (int m = 0; m < 2; m++)
        #pragma unroll
        for (int n = 0; n < 4; n++) wmma::fill_fragment(acc[m][n], 0.f);

    g2_issue(dyn, tid, 0, rows_left, Asrc);
    g2_issue(dyn + STG2, tid, 1, rows_left, Asrc);

    for (int kt = 0; kt < 16; kt++) {
        if (kt < 14) CP_WAIT1(); else CP_WAIT0();
        __syncthreads();
        if (kt + 2 < 16) g2_issue(dyn + ((kt + 2) % 3) * STG2, tid, kt + 2, rows_left, Asrc);
        char* st = dyn + (kt % 3) * STG2;
        __half (*Ah)[LDA2] = reinterpret_cast<__half(*)[LDA2]>(st);
        __half (*Bh)[LDB2] = reinterpret_cast<__half(*)[LDB2]>(st + S2_OFF_BH);
        #pragma unroll
        for (int kk = 0; kk < 32; kk += 16) {
            wmma::fragment<wmma::matrix_a, 16, 16, 16, __half, wmma::row_major> afH[2];
            #pragma unroll
            for (int m = 0; m < 2; m++)
                wmma::load_matrix_sync(afH[m], &Ah[warpM * 32 + m * 16][kk], LDA2);
            #pragma unroll
            for (int n = 0; n < 4; n++) {
                wmma::fragment<wmma::matrix_b, 16, 16, 16, __half, wmma::row_major> bfH;
                wmma::load_matrix_sync(bfH, &Bh[kk][warpN * 64 + n * 16], LDB2);
                #pragma unroll
                for (int m = 0; m < 2; m++)
                    wmma::mma_sync(acc[m][n], afH[m], bfH, acc[m][n]);
            }
        }
    }

    __syncthreads();
    float (*Cs)[LDC1] = reinterpret_cast<float(*)[LDC1]>(dyn);
    #pragma unroll
    for (int m = 0; m < 2; m++)
        #pragma unroll
        for (int n = 0; n < 4; n++)
            wmma::store_matrix_sync(&Cs[warpM * 32 + m * 16][warpN * 64 + n * 16],
                                    acc[m][n], LDC1, wmma::mem_row_major);
    __syncthreads();
    #pragma unroll
    for (int q = 0; q < 32; q++) {
        int idx = q * 256 + tid;
        int r = idx >> 6, c2 = (idx & 63) * 2;
        int gi = i0 + r;
        if (gi < N_NODES) {
            float v0 = Cs[r][c2] + c2S[c2];
            float v1 = Cs[r][c2 + 1] + c2S[c2 + 1];
            #pragma unroll
            for (int t = 0; t < 10; t++) {
                float d = demoS[r][t];
                v0 += d * WgbS[t][c2];
                v1 += d * WgbS[t][c2 + 1];
            }
            float dinv = rsqrtf((float)g_deg[gi]);
            *reinterpret_cast<__half2*>(&g_y2[(size_t)gi * DG + c2]) =
                __floats2half2_rn(dinv * v0, dinv * v1);
        }
    }
}

// ---------------- gather (fp16 y) + fused epilogue ----------------
__global__ __launch_bounds__(256) void k_gather(const float* __restrict__ bg,
                                                const float* __restrict__ Wo) {
    int wid = threadIdx.x >> 5, lane = threadIdx.x & 31;
    int node = blockIdx.x * 8 + wid;
    float dot = 0.f;
    if (node < N_NODES) {
        int deg = g_deg[node];
        int beg = g_off[node];
        int cnt = deg - 1;
        float2 raw = *reinterpret_cast<const float2*>(&g_y2[(size_t)node * DG + lane * 4]);
        __half2 h0 = *reinterpret_cast<__half2*>(&raw.x);
        __half2 h1 = *reinterpret_cast<__half2*>(&raw.y);
        float2 f0 = __half22float2(h0), f1 = __half22float2(h1);
        float4 a = make_float4(f0.x, f0.y, f1.x, f1.y);
        #pragma unroll 4
        for (int j = 0; j < cnt; j++) {
            int s = __ldg(&g_es[beg + j]);
            float2 rw = *reinterpret_cast<const float2*>(&g_y2[(size_t)s * DG + lane * 4]);
            __half2 g0 = *reinterpret_cast<__half2*>(&rw.x);
            __half2 g1 = *reinterpret_cast<__half2*>(&rw.y);
            float2 e0 = __half22float2(g0), e1 = __half22float2(g1);
            a.x += e0.x; a.y += e0.y; a.z += e1.x; a.w += e1.y;
        }
        float dinv = rsqrtf((float)deg);
        float4 bgv = *reinterpret_cast<const float4*>(&bg[lane * 4]);
        float4 wv = *reinterpret_cast<const float4*>(&Wo[lane * 4]);
        dot += fmaxf(dinv * a.x + bgv.x, 0.f) * wv.x;
        dot += fmaxf(dinv * a.y + bgv.y, 0.f) * wv.y;
        dot += fmaxf(dinv * a.z + bgv.z, 0.f) * wv.z;
        dot += fmaxf(dinv * a.w + bgv.w, 0.f) * wv.w;
    }
    #pragma unroll
    for (int o = 16; o; o >>= 1) dot += __shfl_down_sync(0xffffffffu, dot, o);
    __shared__ float part[8];
    if (lane == 0) part[wid] = dot;
    __syncthreads();
    if (threadIdx.x == 0) {
        float s = 0.f;
        #pragma unroll
        for (int w = 0; w < 8; w++) s += part[w];
        atomicAdd(&g_acc, (double)s);
    }
}

__global__ void k_fin(const float* __restrict__ bo, float* __restrict__ out) {
    out[0] = (float)(g_acc * (1.0 / (double)N_NODES) + (double)bo[0]);
}

// ---------------- launch (two-stream fork/join, graph-capturable) ----------------
extern "C" void kernel_launch(void* const* d_in, const int* in_sizes, int n_in,
                              void* d_out, int out_size) {
    const float* x  = (const float*)d_in[0];
    const int*   ei = (const int*)d_in[1];
    const float* W1 = (const float*)d_in[2];
    const float* b1 = (const float*)d_in[3];
    const float* W2 = (const float*)d_in[4];
    const float* b2 = (const float*)d_in[5];
    const float* Wg = (const float*)d_in[6];
    const float* bg = (const float*)d_in[7];
    const float* Wo = (const float*)d_in[8];
    const float* bo = (const float*)d_in[9];
    float* out = (float*)d_out;

    // one-time host-side resources (no device memory)
    static cudaStream_t s1 = nullptr;
    static cudaEvent_t eFork = nullptr, eJoin = nullptr;
    if (s1 == nullptr) {
        cudaStreamCreateWithFlags(&s1, cudaStreamNonBlocking);
        cudaEventCreateWithFlags(&eFork, cudaEventDisableTiming);
        cudaEventCreateWithFlags(&eJoin, cudaEventDisableTiming);
        cudaFuncSetAttribute(k_gemm1, cudaFuncAttributeMaxDynamicSharedMemorySize, DYN1);
        cudaFuncSetAttribute(k_gemm2, cudaFuncAttributeMaxDynamicSharedMemorySize, DYN2);
    }

    // fork: side stream joins the capture via event
    cudaEventRecord(eFork, 0);
    cudaStreamWaitEvent(s1, eFork, 0);

    // main chain (stream 0): split + gemm1
    k_splitx<<<2048, 256>>>(x);
    k_splitw<<<(1024 * 256 + 255) / 256, 256>>>(W1);
    k_gemm1<<<G1_MBLK * 4, 256, DYN1>>>(b1);

    // side chain (s1): edge prep + weight fold (independent buffers)
    k_init<<<(N_NODES + 255) / 256, 256, 0, s1>>>();
    k_pre<<<H1 + 1, 128, 0, s1>>>(W2, Wg, b2);
    k_deg<<<4096, 256, 0, s1>>>(ei);
    k_scan1<<<SCAN_NBLK, SCAN_CHUNK, 0, s1>>>();
    k_scan2<<<1, 128, 0, s1>>>();
    k_scan3<<<SCAN_NBLK, SCAN_CHUNK, 0, s1>>>();
    k_fill<<<4096, 256, 0, s1>>>(ei);
    cudaEventRecord(eJoin, s1);

    // join: gemm2 needs g_deg/g_w23h/g_c2; gather needs g_off/g_es
    cudaStreamWaitEvent(0, eJoin, 0);
    k_gemm2<<<(N_NODES + 127) / 128, 256, DYN2>>>(x, Wg);
    k_gather<<<(N_NODES + 7) / 8, 256>>>(bg, Wo);
    k_fin<<<1, 1>>>(bo, out);
}